// round 1
// baseline (speedup 1.0000x reference)
#include <cuda_runtime.h>
#include <math.h>

// ---------------------------------------------------------------------------
// QANet forward, fp32. Shapes fixed by the problem.
// ---------------------------------------------------------------------------
#define kB 64
#define kD 128
#define kN 400
#define kM 50
#define kH 8
#define kKD 16
#define kNC 4
#define kKW 7
#define kPAD 3

// ------------------------- device scratch (static) -------------------------
__device__ float g_C[kB * kD * kN];        // context activation [B,D,N]
__device__ float g_Q[kB * kD * kM];        // question activation [B,D,M]
__device__ float g_ln[kB * kD * kN];       // LN output scratch (max size)
__device__ float g_dw[kB * kD * kN];       // depthwise-conv scratch
__device__ float g_qkv[kB * 3 * kD * kN];  // packed q,k,v  [B, 384, L]
__device__ float g_ao[kB * kD * kN];       // attention output [B, 128, L]
__device__ float g_Wqkv[3 * kD * kD];      // packed QKV weight [384][128]
__device__ float g_bqkv[3 * kD];
__device__ float g_pe[kD * kN];            // position encoding table [D][N]
__device__ float g_S[kB * kN * kM];
__device__ float g_Sr[kB * kN * kM];
__device__ float g_Sc[kB * kN * kM];
__device__ float g_U[kB * kD * kM];        // U[b,d,m] = sum_n Sc[b,n,m]*C[b,d,n]
__device__ float g_cc[kB * kN];
__device__ float g_qq[kB * kM];

// ------------------------------ PE table ----------------------------------
__global__ void k_pe() {
    int idx = blockIdx.x * blockDim.x + threadIdx.x;
    if (idx >= kD * kN) return;
    int d = idx / kN;
    int l = idx % kN;
    int d0 = d & ~1;
    double f = pow(10000.0, -(double)d0 / (double)kD);
    double a = (double)l * f;
    g_pe[idx] = (d & 1) ? (float)cos(a) : (float)sin(a);
}

__global__ void k_add_pe(const float* __restrict__ x, float* __restrict__ y, int L) {
    int idx = blockIdx.x * blockDim.x + threadIdx.x;
    if (idx >= kB * kD * L) return;
    int d = (idx / L) % kD;
    int l = idx % L;
    y[idx] = x[idx] + g_pe[d * kN + l];
}

// ------------------------------ LayerNorm ----------------------------------
// Per (b,l) over D=128 channels, torch semantics: unbiased std, (x-mu)/(std+eps).
// Block = 128 threads covering 32 positions x 4 channel-groups (coalesced in l).
__global__ void __launch_bounds__(128) k_ln(const float* __restrict__ x,
                                            float* __restrict__ y,
                                            const float* __restrict__ gamma,
                                            const float* __restrict__ beta, int L) {
    int tid = threadIdx.x;
    int lsub = tid & 31;
    int grp = tid >> 5;
    int pos = blockIdx.x * 32 + lsub;
    int P = kB * L;
    bool ok = pos < P;
    int b = ok ? pos / L : 0;
    int l = ok ? pos % L : 0;

    float vals[32];
    float s = 0.f, sq = 0.f;
    if (ok) {
        const float* xp = x + ((size_t)b * kD + grp * 32) * L + l;
#pragma unroll
        for (int k = 0; k < 32; k++) {
            float v = xp[(size_t)k * L];
            vals[k] = v;
            s += v;
            sq += v * v;
        }
    }
    __shared__ float ss[4][32], sb[4][32];
    ss[grp][lsub] = s;
    sb[grp][lsub] = sq;
    __syncthreads();
    float ts = ss[0][lsub] + ss[1][lsub] + ss[2][lsub] + ss[3][lsub];
    float tq = sb[0][lsub] + sb[1][lsub] + sb[2][lsub] + sb[3][lsub];
    float mu = ts * (1.f / 128.f);
    float var = (tq - 128.f * mu * mu) * (1.f / 127.f);
    var = fmaxf(var, 0.f);
    float rin = 1.f / (sqrtf(var) + 1e-6f);
    if (ok) {
        float* yp = y + ((size_t)b * kD + grp * 32) * L + l;
#pragma unroll
        for (int k = 0; k < 32; k++) {
            int d = grp * 32 + k;
            yp[(size_t)k * L] = gamma[d] * (vals[k] - mu) * rin + beta[d];
        }
    }
}

// --------------------------- depthwise conv --------------------------------
__global__ void k_dw(const float* __restrict__ x, float* __restrict__ y,
                     const float* __restrict__ w, const float* __restrict__ bias, int L) {
    int idx = blockIdx.x * blockDim.x + threadIdx.x;
    if (idx >= kB * kD * L) return;
    int r = idx % (kD * L);
    int d = r / L;
    int l = r % L;
    const float* base = x + (size_t)(idx - l);  // row start (b,d,0)
    float a = bias[d];
#pragma unroll
    for (int k = 0; k < kKW; k++) {
        int j = l + k - kPAD;
        if (j >= 0 && j < L) a += w[d * kKW + k] * base[j];
    }
    y[idx] = a;
}

// ------------------------------- GEMM --------------------------------------
// out[b, e, l] = act( sum_d W(e,d) * X[b,d,l] + bias[e] ) (+ res[b,e,l])
// TR=false: W stored [e][Din]. TR=true: W stored [d][Etot].
// Din fixed = 128. E tile = 128 per blockIdx.y. L tile = 32 per blockIdx.x.
template <bool TR, bool RELU, bool RES>
__global__ void __launch_bounds__(256) k_gemm(const float* __restrict__ X,
                                              const float* __restrict__ W,
                                              const float* __restrict__ bias,
                                              const float* res, float* out,
                                              int L, int Etot) {
    __shared__ float Xs[32][33];
    __shared__ float Ws[32][132];  // stride 132 floats -> 16B aligned rows
    int tid = threadIdx.x;
    int l = tid & 31;
    int eg = tid >> 5;
    int l0 = blockIdx.x * 32;
    int et = blockIdx.y * 128;
    int b = blockIdx.z;

    float acc[16];
#pragma unroll
    for (int j = 0; j < 16; j++) acc[j] = 0.f;

    for (int d0 = 0; d0 < 128; d0 += 32) {
#pragma unroll
        for (int r = 0; r < 4; r++) {
            int idx = tid + r * 256;
            int dd = idx >> 5;
            int ll = idx & 31;
            int lg = l0 + ll;
            Xs[dd][ll] = (lg < L) ? X[((size_t)b * 128 + d0 + dd) * L + lg] : 0.f;
        }
#pragma unroll
        for (int r = 0; r < 16; r++) {
            int idx = tid + r * 256;
            if (TR) {
                int dd = idx >> 7;
                int e = idx & 127;
                Ws[dd][e] = W[(size_t)(d0 + dd) * Etot + et + e];
            } else {
                int e = idx >> 5;
                int dd = idx & 31;
                Ws[dd][e] = W[(size_t)(et + e) * 128 + d0 + dd];
            }
        }
        __syncthreads();
#pragma unroll
        for (int dd = 0; dd < 32; dd++) {
            float xv = Xs[dd][l];
            const float4* wr = (const float4*)&Ws[dd][eg * 16];
            float4 w0 = wr[0], w1 = wr[1], w2 = wr[2], w3 = wr[3];
            acc[0] += w0.x * xv;  acc[1] += w0.y * xv;
            acc[2] += w0.z * xv;  acc[3] += w0.w * xv;
            acc[4] += w1.x * xv;  acc[5] += w1.y * xv;
            acc[6] += w1.z * xv;  acc[7] += w1.w * xv;
            acc[8] += w2.x * xv;  acc[9] += w2.y * xv;
            acc[10] += w2.z * xv; acc[11] += w2.w * xv;
            acc[12] += w3.x * xv; acc[13] += w3.y * xv;
            acc[14] += w3.z * xv; acc[15] += w3.w * xv;
        }
        __syncthreads();
    }
    int lg = l0 + l;
    if (lg < L) {
#pragma unroll
        for (int j = 0; j < 16; j++) {
            int e = et + eg * 16 + j;
            float v = acc[j] + bias[e];
            if (RELU) v = fmaxf(v, 0.f);
            size_t oi = ((size_t)b * Etot + e) * L + lg;
            if (RES) v += res[oi];
            out[oi] = v;
        }
    }
}

// ----------------------------- QKV packing ---------------------------------
__global__ void k_pack_qkv(const float* __restrict__ Wq, const float* __restrict__ Wk,
                           const float* __restrict__ Wv, const float* __restrict__ bq,
                           const float* __restrict__ bk, const float* __restrict__ bv) {
    int idx = blockIdx.x * blockDim.x + threadIdx.x;
    if (idx < 3 * 128 * 128) {
        int e = idx >> 7;
        int d = idx & 127;
        int qv = e >> 7;
        int hk = e & 127;
        int h = hk >> 4;
        int kk = hk & 15;
        const float* src = (qv == 0) ? Wq : (qv == 1 ? Wk : Wv);
        g_Wqkv[idx] = src[((size_t)h * 128 + d) * 16 + kk];
    }
    if (idx < 384) {
        int qv = idx >> 7;
        int hk = idx & 127;
        const float* srcb = (qv == 0) ? bq : (qv == 1 ? bk : bv);
        g_bqkv[idx] = srcb[hk];
    }
}

// ----------------------------- attention core ------------------------------
// qkv layout [B, 384, L]: q ch 0..127, k ch 128..255, v ch 256..383 (c = h*16+kd)
// One thread per query row; K/V tiles staged in smem, online softmax.
__global__ void __launch_bounds__(256) k_attn(const float* __restrict__ qkv,
                                              const float* __restrict__ mask,
                                              float* __restrict__ o, int L) {
    const int KT = 64;
    __shared__ float ks[KT][17], vs[KT][17], ms[KT];
    int tid = threadIdx.x;
    int bh = blockIdx.y;
    int b = bh >> 3;
    int h = bh & 7;
    int i = blockIdx.x * 256 + tid;
    bool act = i < L;

    float q[16];
    if (act) {
        const float* qp = qkv + ((size_t)b * 384 + h * 16) * L + i;
#pragma unroll
        for (int c = 0; c < 16; c++) q[c] = qp[(size_t)c * L] * 0.25f;  // /sqrt(16)
    }
    float m = -INFINITY, lsum = 0.f;
    float acc[16];
#pragma unroll
    for (int c = 0; c < 16; c++) acc[c] = 0.f;

    for (int j0 = 0; j0 < L; j0 += KT) {
        int cnt = min(KT, L - j0);
        for (int idx = tid; idx < 16 * KT; idx += 256) {
            int c = idx >> 6;
            int t = idx & 63;
            if (t < cnt) {
                ks[t][c] = qkv[((size_t)b * 384 + 128 + h * 16 + c) * L + j0 + t];
                vs[t][c] = qkv[((size_t)b * 384 + 256 + h * 16 + c) * L + j0 + t];
            }
        }
        if (tid < KT && tid < cnt) ms[tid] = mask[(size_t)b * L + j0 + tid];
        __syncthreads();
        if (act) {
            for (int t = 0; t < cnt; t++) {
                float s = 0.f;
#pragma unroll
                for (int c = 0; c < 16; c++) s += q[c] * ks[t][c];
                s -= 1e30f * (1.f - ms[t]);
                float nm = fmaxf(m, s);
                float sc = expf(m - nm);
                float p = expf(s - nm);
                lsum = lsum * sc + p;
#pragma unroll
                for (int c = 0; c < 16; c++) acc[c] = acc[c] * sc + p * vs[t][c];
                m = nm;
            }
        }
        __syncthreads();
    }
    if (act) {
        float r = 1.f / lsum;
        float* op = o + ((size_t)b * 128 + h * 16) * L + i;
#pragma unroll
        for (int c = 0; c < 16; c++) op[(size_t)c * L] = acc[c] * r;
    }
}

// ------------------------------ CQ attention -------------------------------
__global__ void k_dot(const float* __restrict__ X, const float* __restrict__ w,
                      float* __restrict__ out, int L) {
    int idx = blockIdx.x * blockDim.x + threadIdx.x;
    if (idx >= kB * L) return;
    int b = idx / L;
    int pos = idx % L;
    const float* xp = X + (size_t)b * kD * L + pos;
    float a = 0.f;
#pragma unroll 8
    for (int d = 0; d < kD; d++) a += w[d] * xp[(size_t)d * L];
    out[idx] = a;
}

__global__ void k_S(const float* __restrict__ C, const float* __restrict__ Qm,
                    const float* __restrict__ wm, const float* __restrict__ b0) {
    int idx = blockIdx.x * blockDim.x + threadIdx.x;
    if (idx >= kB * kN * kM) return;
    int mm = idx % kM;
    int n = (idx / kM) % kN;
    int b = idx / (kN * kM);
    float a = g_cc[b * kN + n] + g_qq[b * kM + mm] + b0[0];
    const float* cp = C + (size_t)b * kD * kN + n;
    const float* qp = Qm + (size_t)b * kD * kM + mm;
#pragma unroll 8
    for (int d = 0; d < kD; d++) a += cp[(size_t)d * kN] * wm[d] * qp[(size_t)d * kM];
    g_S[idx] = a;
}

// softmax over m (row), masked by q_mask. One warp per (b,n).
__global__ void k_smrow(const float* __restrict__ qmask) {
    int w = (blockIdx.x * blockDim.x + threadIdx.x) >> 5;
    int lane = threadIdx.x & 31;
    if (w >= kB * kN) return;
    int b = w / kN;
    const float* row = g_S + (size_t)w * kM;
    int m0 = lane, m1 = lane + 32;
    float v0 = row[m0] - 1e30f * (1.f - qmask[b * kM + m0]);
    float v1 = (m1 < kM) ? row[m1] - 1e30f * (1.f - qmask[b * kM + m1]) : -INFINITY;
    float mx = fmaxf(v0, v1);
#pragma unroll
    for (int o = 16; o; o >>= 1) mx = fmaxf(mx, __shfl_xor_sync(0xffffffff, mx, o));
    float e0 = expf(v0 - mx);
    float e1 = (m1 < kM) ? expf(v1 - mx) : 0.f;
    float s = e0 + e1;
#pragma unroll
    for (int o = 16; o; o >>= 1) s += __shfl_xor_sync(0xffffffff, s, o);
    float r = 1.f / s;
    float* orow = g_Sr + (size_t)w * kM;
    orow[m0] = e0 * r;
    if (m1 < kM) orow[m1] = e1 * r;
}

// softmax over n (column), masked by c_mask. One warp per (b,m).
__global__ void k_smcol(const float* __restrict__ cmask) {
    int w = (blockIdx.x * blockDim.x + threadIdx.x) >> 5;
    int lane = threadIdx.x & 31;
    if (w >= kB * kM) return;
    int b = w / kM;
    int mcol = w % kM;
    float v[13];
#pragma unroll
    for (int k = 0; k < 13; k++) {
        int n = lane + k * 32;
        v[k] = (n < kN) ? g_S[((size_t)b * kN + n) * kM + mcol] -
                              1e30f * (1.f - cmask[b * kN + n])
                        : -INFINITY;
    }
    float mx = v[0];
#pragma unroll
    for (int k = 1; k < 13; k++) mx = fmaxf(mx, v[k]);
#pragma unroll
    for (int o = 16; o; o >>= 1) mx = fmaxf(mx, __shfl_xor_sync(0xffffffff, mx, o));
    float s = 0.f;
    float e[13];
#pragma unroll
    for (int k = 0; k < 13; k++) {
        int n = lane + k * 32;
        e[k] = (n < kN) ? expf(v[k] - mx) : 0.f;
        s += e[k];
    }
#pragma unroll
    for (int o = 16; o; o >>= 1) s += __shfl_xor_sync(0xffffffff, s, o);
    float r = 1.f / s;
#pragma unroll
    for (int k = 0; k < 13; k++) {
        int n = lane + k * 32;
        if (n < kN) g_Sc[((size_t)b * kN + n) * kM + mcol] = e[k] * r;
    }
}

__global__ void k_U(const float* __restrict__ C) {
    int idx = blockIdx.x * blockDim.x + threadIdx.x;
    if (idx >= kB * kD * kM) return;
    int mm = idx % kM;
    int d = (idx / kM) % kD;
    int b = idx / (kD * kM);
    const float* cp = C + ((size_t)b * kD + d) * kN;
    const float* sp = g_Sc + (size_t)b * kN * kM + mm;
    float a = 0.f;
#pragma unroll 8
    for (int n = 0; n < kN; n++) a += sp[(size_t)n * kM] * cp[n];
    g_U[idx] = a;
}

__global__ void __launch_bounds__(128) k_out(const float* __restrict__ C,
                                             const float* __restrict__ Qm,
                                             float* __restrict__ out) {
    int bn = blockIdx.x;
    int b = bn / kN;
    int n = bn % kN;
    int d = threadIdx.x;
    __shared__ float sr[kM];
    if (d < kM) sr[d] = g_Sr[(size_t)bn * kM + d];
    __syncthreads();
    const float* qp = Qm + ((size_t)b * kD + d) * kM;
    const float* up = g_U + ((size_t)b * kD + d) * kM;
    float a = 0.f, bt = 0.f;
#pragma unroll
    for (int mm = 0; mm < kM; mm++) {
        float s = sr[mm];
        a += s * qp[mm];
        bt += s * up[mm];
    }
    float c = C[((size_t)b * kD + d) * kN + n];
    size_t base = (size_t)bn * 512;
    out[base + d] = c;
    out[base + 128 + d] = a;
    out[base + 256 + d] = c * a;
    out[base + 384 + d] = c * bt;
}

// ------------------------------- host side ---------------------------------
static inline int ceil_div(int a, int b) { return (a + b - 1) / b; }

extern "C" void kernel_launch(void* const* d_in, const int* in_sizes, int n_in,
                              void* d_out, int out_size) {
    (void)in_sizes; (void)n_in; (void)out_size;
    const float* ctx   = (const float*)d_in[0];
    const float* qst   = (const float*)d_in[1];
    const float* cmask = (const float*)d_in[2];
    const float* qmask = (const float*)d_in[3];
    const float* ln_g  = (const float*)d_in[4];
    const float* ln_b  = (const float*)d_in[5];
    const float* dww   = (const float*)d_in[6];
    const float* dwb   = (const float*)d_in[7];
    const float* pww   = (const float*)d_in[8];
    const float* pwb   = (const float*)d_in[9];
    const float* Wq    = (const float*)d_in[10];
    const float* bq    = (const float*)d_in[11];
    const float* Wk    = (const float*)d_in[12];
    const float* bk    = (const float*)d_in[13];
    const float* Wv    = (const float*)d_in[14];
    const float* bv    = (const float*)d_in[15];
    const float* Wo    = (const float*)d_in[16];
    const float* bo    = (const float*)d_in[17];
    const float* Wfc   = (const float*)d_in[18];
    const float* bfc   = (const float*)d_in[19];
    const float* cq_wc = (const float*)d_in[20];
    const float* cq_wq = (const float*)d_in[21];
    const float* cq_wm = (const float*)d_in[22];
    const float* cq_b  = (const float*)d_in[23];

    float *pC, *pQ, *pln, *pdw, *pqkv, *pao, *pcc, *pqq;
    cudaGetSymbolAddress((void**)&pC, g_C);
    cudaGetSymbolAddress((void**)&pQ, g_Q);
    cudaGetSymbolAddress((void**)&pln, g_ln);
    cudaGetSymbolAddress((void**)&pdw, g_dw);
    cudaGetSymbolAddress((void**)&pqkv, g_qkv);
    cudaGetSymbolAddress((void**)&pao, g_ao);
    cudaGetSymbolAddress((void**)&pcc, g_cc);
    cudaGetSymbolAddress((void**)&pqq, g_qq);
    float* pWqkv; cudaGetSymbolAddress((void**)&pWqkv, g_Wqkv);
    float* pbqkv; cudaGetSymbolAddress((void**)&pbqkv, g_bqkv);

    k_pe<<<ceil_div(kD * kN, 256), 256>>>();
    k_pack_qkv<<<ceil_div(3 * 128 * 128, 256), 256>>>(Wq, Wk, Wv, bq, bk, bv);

    // --------- encoder block for one sequence ---------
    auto run_block = [&](const float* emb, float* act, const float* msk, int L) {
        int P = kB * kD * L;
        int lt = ceil_div(L, 32);
        k_add_pe<<<ceil_div(P, 256), 256>>>(emb, act, L);
        for (int i = 0; i < kNC; i++) {
            k_ln<<<ceil_div(kB * L, 32), 128>>>(act, pln, ln_g, ln_b, L);
            k_dw<<<ceil_div(P, 256), 256>>>(pln, pdw, dww + (size_t)i * kD * kKW,
                                            dwb + (size_t)i * kD, L);
            k_gemm<false, true, true><<<dim3(lt, 1, kB), 256>>>(
                pdw, pww + (size_t)i * kD * kD, pwb + (size_t)i * kD, act, act, L, kD);
        }
        // self-attention
        k_ln<<<ceil_div(kB * L, 32), 128>>>(act, pln, ln_g, ln_b, L);
        k_gemm<false, false, false><<<dim3(lt, 3, kB), 256>>>(
            pln, pWqkv, pbqkv, nullptr, pqkv, L, 384);
        k_attn<<<dim3(ceil_div(L, 256), kB * kH), 256>>>(pqkv, msk, pao, L);
        k_gemm<true, false, true><<<dim3(lt, 1, kB), 256>>>(pao, Wo, bo, act, act, L, kD);
        // FFN
        k_ln<<<ceil_div(kB * L, 32), 128>>>(act, pln, ln_g, ln_b, L);
        k_gemm<false, false, true><<<dim3(lt, 1, kB), 256>>>(pln, Wfc, bfc, act, act, L, kD);
    };

    run_block(ctx, pC, cmask, kN);
    run_block(qst, pQ, qmask, kM);

    // --------- context-query attention ---------
    k_dot<<<ceil_div(kB * kN, 256), 256>>>(pC, cq_wc, pcc, kN);
    k_dot<<<ceil_div(kB * kM, 256), 256>>>(pQ, cq_wq, pqq, kM);
    k_S<<<ceil_div(kB * kN * kM, 256), 256>>>(pC, pQ, cq_wm, cq_b);
    k_smrow<<<ceil_div(kB * kN, 8), 256>>>(qmask);
    k_smcol<<<ceil_div(kB * kM, 8), 256>>>(cmask);
    k_U<<<ceil_div(kB * kD * kM, 256), 256>>>(pC);
    k_out<<<kB * kN, 128>>>(pC, pQ, (float*)d_out);
}

// round 2
// speedup vs baseline: 1.4605x; 1.4605x over previous
#include <cuda_runtime.h>
#include <math.h>

// ---------------------------------------------------------------------------
// QANet forward, fp32 with packed f32x2 FMA on sm_103a.
// ---------------------------------------------------------------------------
#define kB 64
#define kD 128
#define kN 400
#define kM 50
#define kH 8
#define kKD 16
#define kNC 4
#define kKW 7
#define kPAD 3

typedef unsigned long long u64;

__device__ __forceinline__ u64 pk2(float lo, float hi) {
    u64 r; asm("mov.b64 %0,{%1,%2};" : "=l"(r) : "f"(lo), "f"(hi)); return r;
}
__device__ __forceinline__ void upk2(u64 v, float& lo, float& hi) {
    asm("mov.b64 {%0,%1},%2;" : "=f"(lo), "=f"(hi) : "l"(v));
}
__device__ __forceinline__ u64 fma2(u64 a, u64 b, u64 c) {
    u64 d; asm("fma.rn.f32x2 %0,%1,%2,%3;" : "=l"(d) : "l"(a), "l"(b), "l"(c)); return d;
}
__device__ __forceinline__ u64 mul2(u64 a, u64 b) {
    u64 d; asm("mul.rn.f32x2 %0,%1,%2;" : "=l"(d) : "l"(a), "l"(b)); return d;
}

// ------------------------- device scratch (static) -------------------------
__device__ float g_C[kB * kD * kN];        // context activation [B,D,N]
__device__ float g_Q[kB * kD * kM];        // question activation [B,D,M]
__device__ float g_ln[kB * kD * kN];       // LN output scratch
__device__ float g_dw[kB * kD * kN];       // depthwise-conv scratch
__device__ float g_qkv[kB * 3 * kD * kN];  // packed q,k,v  [B, 384, L]
__device__ float g_ao[kB * kD * kN];       // attention output [B, 128, L]
__device__ float g_Wqkv[3 * kD * kD];      // packed QKV weight [384][128]
__device__ float g_bqkv[3 * kD];
__device__ float g_pe[kD * kN];            // position encoding table [D][N]
__device__ float g_S[kB * kM * kN];        // S[b][m][n]
__device__ float g_Sr[kB * kM * kN];       // row-softmax (over m), layout [b][m][n]
__device__ float g_Sc[kB * kM * kN];       // col-softmax (over n), layout [b][m][n]
__device__ float g_U[kB * kM * kD];        // U[b][m][d]
__device__ float g_Ct[kB * kN * kD];       // C transposed [b][n][d]
__device__ float g_Qt[kB * kM * kD];       // Q transposed [b][m][d]
__device__ float g_Qw[kB * kM * kD];       // Qt * wm[d]
__device__ float g_cc[kB * kN];
__device__ float g_qq[kB * kM];

// ------------------------------ PE table ----------------------------------
__global__ void k_pe() {
    int idx = blockIdx.x * blockDim.x + threadIdx.x;
    if (idx >= kD * kN) return;
    int d = idx / kN;
    int l = idx % kN;
    int d0 = d & ~1;
    double f = pow(10000.0, -(double)d0 / (double)kD);
    double a = (double)l * f;
    g_pe[idx] = (d & 1) ? (float)cos(a) : (float)sin(a);
}

__global__ void k_add_pe(const float* __restrict__ x, float* __restrict__ y, int L) {
    int idx = blockIdx.x * blockDim.x + threadIdx.x;
    if (idx >= kB * kD * L) return;
    int d = (idx / L) % kD;
    int l = idx % L;
    y[idx] = x[idx] + g_pe[d * kN + l];
}

// ------------------------------ LayerNorm ----------------------------------
__global__ void __launch_bounds__(128) k_ln(const float* __restrict__ x,
                                            float* __restrict__ y,
                                            const float* __restrict__ gamma,
                                            const float* __restrict__ beta, int L) {
    int tid = threadIdx.x;
    int lsub = tid & 31;
    int grp = tid >> 5;
    int pos = blockIdx.x * 32 + lsub;
    int P = kB * L;
    bool ok = pos < P;
    int b = ok ? pos / L : 0;
    int l = ok ? pos % L : 0;

    float vals[32];
    float s = 0.f, sq = 0.f;
    if (ok) {
        const float* xp = x + ((size_t)b * kD + grp * 32) * L + l;
#pragma unroll
        for (int k = 0; k < 32; k++) {
            float v = xp[(size_t)k * L];
            vals[k] = v;
            s += v;
            sq += v * v;
        }
    }
    __shared__ float ss[4][32], sb[4][32];
    ss[grp][lsub] = s;
    sb[grp][lsub] = sq;
    __syncthreads();
    float ts = ss[0][lsub] + ss[1][lsub] + ss[2][lsub] + ss[3][lsub];
    float tq = sb[0][lsub] + sb[1][lsub] + sb[2][lsub] + sb[3][lsub];
    float mu = ts * (1.f / 128.f);
    float var = (tq - 128.f * mu * mu) * (1.f / 127.f);
    var = fmaxf(var, 0.f);
    float rin = 1.f / (sqrtf(var) + 1e-6f);
    if (ok) {
        float* yp = y + ((size_t)b * kD + grp * 32) * L + l;
#pragma unroll
        for (int k = 0; k < 32; k++) {
            int d = grp * 32 + k;
            yp[(size_t)k * L] = gamma[d] * (vals[k] - mu) * rin + beta[d];
        }
    }
}

// --------------------------- depthwise conv --------------------------------
__global__ void k_dw(const float* __restrict__ x, float* __restrict__ y,
                     const float* __restrict__ w, const float* __restrict__ bias, int L) {
    int idx = blockIdx.x * blockDim.x + threadIdx.x;
    if (idx >= kB * kD * L) return;
    int r = idx % (kD * L);
    int d = r / L;
    int l = r % L;
    const float* base = x + (size_t)(idx - l);
    float a = bias[d];
#pragma unroll
    for (int k = 0; k < kKW; k++) {
        int j = l + k - kPAD;
        if (j >= 0 && j < L) a += w[d * kKW + k] * base[j];
    }
    y[idx] = a;
}

// ------------------------------- GEMM --------------------------------------
// out[b, e, l] = act( sum_d W(e,d) * X[b,d,l] + bias[e] ) (+ res[b,e,l])
// Inner loop uses fma.rn.f32x2: 8 packed FMAs per K-step per thread (16 MAC).
template <bool TR, bool RELU, bool RES>
__global__ void __launch_bounds__(256) k_gemm(const float* __restrict__ X,
                                              const float* __restrict__ W,
                                              const float* __restrict__ bias,
                                              const float* res, float* out,
                                              int L, int Etot) {
    __shared__ float Xs[32][33];
    __shared__ float Ws[32][132];
    int tid = threadIdx.x;
    int l = tid & 31;
    int eg = tid >> 5;
    int l0 = blockIdx.x * 32;
    int et = blockIdx.y * 128;
    int b = blockIdx.z;

    u64 acc[8] = {0, 0, 0, 0, 0, 0, 0, 0};

    for (int d0 = 0; d0 < 128; d0 += 32) {
#pragma unroll
        for (int r = 0; r < 4; r++) {
            int idx = tid + r * 256;
            int dd = idx >> 5;
            int ll = idx & 31;
            int lg = l0 + ll;
            Xs[dd][ll] = (lg < L) ? X[((size_t)b * 128 + d0 + dd) * L + lg] : 0.f;
        }
#pragma unroll
        for (int r = 0; r < 16; r++) {
            int idx = tid + r * 256;
            if (TR) {
                int dd = idx >> 7;
                int e = idx & 127;
                Ws[dd][e] = W[(size_t)(d0 + dd) * Etot + et + e];
            } else {
                int e = idx >> 5;
                int dd = idx & 31;
                Ws[dd][e] = W[(size_t)(et + e) * 128 + d0 + dd];
            }
        }
        __syncthreads();
#pragma unroll
        for (int dd = 0; dd < 32; dd++) {
            float xv = Xs[dd][l];
            u64 xx = pk2(xv, xv);
            const ulonglong2* wr = (const ulonglong2*)&Ws[dd][eg * 16];
            ulonglong2 w0 = wr[0], w1 = wr[1], w2 = wr[2], w3 = wr[3];
            acc[0] = fma2(xx, w0.x, acc[0]);
            acc[1] = fma2(xx, w0.y, acc[1]);
            acc[2] = fma2(xx, w1.x, acc[2]);
            acc[3] = fma2(xx, w1.y, acc[3]);
            acc[4] = fma2(xx, w2.x, acc[4]);
            acc[5] = fma2(xx, w2.y, acc[5]);
            acc[6] = fma2(xx, w3.x, acc[6]);
            acc[7] = fma2(xx, w3.y, acc[7]);
        }
        __syncthreads();
    }
    int lg = l0 + l;
    if (lg < L) {
#pragma unroll
        for (int j = 0; j < 8; j++) {
            float v0, v1;
            upk2(acc[j], v0, v1);
            int e = et + eg * 16 + 2 * j;
#pragma unroll
            for (int t = 0; t < 2; t++) {
                float v = (t == 0 ? v0 : v1) + bias[e + t];
                if (RELU) v = fmaxf(v, 0.f);
                size_t oi = ((size_t)b * Etot + e + t) * L + lg;
                if (RES) v += res[oi];
                out[oi] = v;
            }
        }
    }
}

// ----------------------------- QKV packing ---------------------------------
__global__ void k_pack_qkv(const float* __restrict__ Wq, const float* __restrict__ Wk,
                           const float* __restrict__ Wv, const float* __restrict__ bq,
                           const float* __restrict__ bk, const float* __restrict__ bv) {
    int idx = blockIdx.x * blockDim.x + threadIdx.x;
    if (idx < 3 * 128 * 128) {
        int e = idx >> 7;
        int d = idx & 127;
        int qv = e >> 7;
        int hk = e & 127;
        int h = hk >> 4;
        int kk = hk & 15;
        const float* src = (qv == 0) ? Wq : (qv == 1 ? Wk : Wv);
        g_Wqkv[idx] = src[((size_t)h * 128 + d) * 16 + kk];
    }
    if (idx < 384) {
        int qv = idx >> 7;
        int hk = idx & 127;
        const float* srcb = (qv == 0) ? bq : (qv == 1 ? bk : bv);
        g_bqkv[idx] = srcb[hk];
    }
}

// ----------------------------- attention core ------------------------------
// qkv layout [B, 384, L]. K/V staged in smem as packed f32x2 pairs.
__global__ void __launch_bounds__(256) k_attn(const float* __restrict__ qkv,
                                              const float* __restrict__ mask,
                                              float* __restrict__ o, int L) {
    const int KT = 64;
    __shared__ u64 ks[KT][9], vs[KT][9];
    __shared__ float ms[KT];
    int tid = threadIdx.x;
    int bh = blockIdx.y;
    int b = bh >> 3;
    int h = bh & 7;
    int i = blockIdx.x * 256 + tid;
    bool act = i < L;

    u64 q2[8];
    if (act) {
        const float* qp = qkv + ((size_t)b * 384 + h * 16) * L + i;
#pragma unroll
        for (int c = 0; c < 8; c++)
            q2[c] = pk2(qp[(size_t)(2 * c) * L] * 0.25f, qp[(size_t)(2 * c + 1) * L] * 0.25f);
    }
    float m = -INFINITY, lsum = 0.f;
    u64 acc[8] = {0, 0, 0, 0, 0, 0, 0, 0};

    for (int j0 = 0; j0 < L; j0 += KT) {
        int cnt = min(KT, L - j0);
        for (int idx = tid; idx < 8 * KT; idx += 256) {
            int c = idx >> 6;
            int t = idx & 63;
            if (t < cnt) {
                const float* kp = qkv + ((size_t)b * 384 + 128 + h * 16 + 2 * c) * L + j0 + t;
                ks[t][c] = pk2(kp[0], kp[(size_t)L]);
                const float* vp = kp + (size_t)128 * L;
                vs[t][c] = pk2(vp[0], vp[(size_t)L]);
            }
        }
        if (tid < KT && tid < cnt) ms[tid] = mask[(size_t)b * L + j0 + tid];
        __syncthreads();
        if (act) {
            for (int t = 0; t < cnt; t++) {
                u64 s2 = 0;
#pragma unroll
                for (int c = 0; c < 8; c++) s2 = fma2(q2[c], ks[t][c], s2);
                float slo, shi;
                upk2(s2, slo, shi);
                float s = slo + shi - 1e30f * (1.f - ms[t]);
                float nm = fmaxf(m, s);
                float sc = __expf(m - nm);
                float p = __expf(s - nm);
                lsum = lsum * sc + p;
                u64 scp = pk2(sc, sc), pp = pk2(p, p);
#pragma unroll
                for (int c = 0; c < 8; c++) acc[c] = fma2(pp, vs[t][c], mul2(scp, acc[c]));
                m = nm;
            }
        }
        __syncthreads();
    }
    if (act) {
        float r = 1.f / lsum;
        float* op = o + ((size_t)b * 128 + h * 16) * L + i;
#pragma unroll
        for (int c = 0; c < 8; c++) {
            float lo, hi;
            upk2(acc[c], lo, hi);
            op[(size_t)(2 * c) * L] = lo * r;
            op[(size_t)(2 * c + 1) * L] = hi * r;
        }
    }
}

// ------------------------------ transposes ---------------------------------
__global__ void k_trC(const float* __restrict__ X, float* __restrict__ Y, int L) {
    __shared__ float t[32][33];
    int b = blockIdx.z, d0 = blockIdx.y * 32, l0 = blockIdx.x * 32;
    int tx = threadIdx.x, ty = threadIdx.y;
#pragma unroll
    for (int k = 0; k < 4; k++) {
        int l = l0 + tx;
        t[ty + 8 * k][tx] = (l < L) ? X[((size_t)b * 128 + d0 + ty + 8 * k) * L + l] : 0.f;
    }
    __syncthreads();
#pragma unroll
    for (int k = 0; k < 4; k++) {
        int l = l0 + ty + 8 * k;
        if (l < L) Y[((size_t)b * L + l) * 128 + d0 + tx] = t[tx][ty + 8 * k];
    }
}

__global__ void k_trQ(const float* __restrict__ X, float* __restrict__ Yt,
                      float* __restrict__ Yw, const float* __restrict__ wm) {
    __shared__ float t[32][33];
    int b = blockIdx.z, d0 = blockIdx.y * 32, l0 = blockIdx.x * 32;
    int tx = threadIdx.x, ty = threadIdx.y;
#pragma unroll
    for (int k = 0; k < 4; k++) {
        int l = l0 + tx;
        t[ty + 8 * k][tx] = (l < kM) ? X[((size_t)b * 128 + d0 + ty + 8 * k) * kM + l] : 0.f;
    }
    __syncthreads();
    float w = wm[d0 + tx];
#pragma unroll
    for (int k = 0; k < 4; k++) {
        int l = l0 + ty + 8 * k;
        if (l < kM) {
            float v = t[tx][ty + 8 * k];
            size_t oi = ((size_t)b * kM + l) * 128 + d0 + tx;
            Yt[oi] = v;
            Yw[oi] = v * w;
        }
    }
}

// ------------------------------ CQ attention -------------------------------
__global__ void k_dot(const float* __restrict__ X, const float* __restrict__ w,
                      float* __restrict__ out, int L) {
    int idx = blockIdx.x * blockDim.x + threadIdx.x;
    if (idx >= kB * L) return;
    int b = idx / L;
    int pos = idx % L;
    const float* xp = X + (size_t)b * kD * L + pos;
    float a = 0.f;
#pragma unroll 8
    for (int d = 0; d < kD; d++) a += w[d] * xp[(size_t)d * L];
    out[idx] = a;
}

// S[b][m][n] = sum_d Qw[b][m][d] * C[b][d][n] + cc[b][n] + qq[b][m] + b0
__global__ void __launch_bounds__(256) k_sgemm(const float* __restrict__ X,
                                               const float* __restrict__ Qw,
                                               const float* __restrict__ cc,
                                               const float* __restrict__ qq,
                                               const float* __restrict__ b0,
                                               float* __restrict__ S) {
    __shared__ float Xs[32][33];
    __shared__ float Ws[32][68];
    int tid = threadIdx.x;
    int l = tid & 31;
    int eg = tid >> 5;
    int l0 = blockIdx.x * 32;
    int b = blockIdx.y;
    u64 acc[4] = {0, 0, 0, 0};

    for (int d0 = 0; d0 < 128; d0 += 32) {
#pragma unroll
        for (int r = 0; r < 4; r++) {
            int idx = tid + r * 256;
            int dd = idx >> 5, ll = idx & 31;
            int lg = l0 + ll;
            Xs[dd][ll] = (lg < kN) ? X[((size_t)b * 128 + d0 + dd) * kN + lg] : 0.f;
        }
#pragma unroll
        for (int r = 0; r < 8; r++) {
            int idx = tid + r * 256;
            int dd = idx >> 6;
            int e = idx & 63;
            Ws[dd][e] = (e < kM) ? Qw[((size_t)b * kM + e) * 128 + d0 + dd] : 0.f;
        }
        __syncthreads();
#pragma unroll
        for (int dd = 0; dd < 32; dd++) {
            float xv = Xs[dd][l];
            u64 xx = pk2(xv, xv);
            const ulonglong2* wr = (const ulonglong2*)&Ws[dd][eg * 8];
            ulonglong2 w0 = wr[0], w1 = wr[1];
            acc[0] = fma2(xx, w0.x, acc[0]);
            acc[1] = fma2(xx, w0.y, acc[1]);
            acc[2] = fma2(xx, w1.x, acc[2]);
            acc[3] = fma2(xx, w1.y, acc[3]);
        }
        __syncthreads();
    }
    int lg = l0 + l;
    if (lg < kN) {
        float base = cc[b * kN + lg] + b0[0];
#pragma unroll
        for (int j = 0; j < 4; j++) {
            float v0, v1;
            upk2(acc[j], v0, v1);
            int e0 = eg * 8 + 2 * j;
            if (e0 < kM) S[((size_t)b * kM + e0) * kN + lg] = v0 + base + qq[b * kM + e0];
            if (e0 + 1 < kM) S[((size_t)b * kM + e0 + 1) * kN + lg] = v1 + base + qq[b * kM + e0 + 1];
        }
    }
}

// softmax over m per (b,n); S layout [b][m][n] so loads are coalesced in n.
__global__ void k_smrow(const float* __restrict__ qmask) {
    int idx = blockIdx.x * blockDim.x + threadIdx.x;
    if (idx >= kB * kN) return;
    int b = idx / kN;
    int n = idx % kN;
    float v[kM];
    float mx = -INFINITY;
#pragma unroll
    for (int m = 0; m < kM; m++) {
        v[m] = g_S[((size_t)b * kM + m) * kN + n] - 1e30f * (1.f - qmask[b * kM + m]);
        mx = fmaxf(mx, v[m]);
    }
    float s = 0.f;
#pragma unroll
    for (int m = 0; m < kM; m++) {
        v[m] = __expf(v[m] - mx);
        s += v[m];
    }
    float r = 1.f / s;
#pragma unroll
    for (int m = 0; m < kM; m++) g_Sr[((size_t)b * kM + m) * kN + n] = v[m] * r;
}

// softmax over n per (b,m); one warp per contiguous row of 400.
__global__ void k_smcol(const float* __restrict__ cmask) {
    int w = (blockIdx.x * blockDim.x + threadIdx.x) >> 5;
    int lane = threadIdx.x & 31;
    if (w >= kB * kM) return;
    int b = w / kM;
    const float* row = g_S + (size_t)w * kN;
    const float* mrow = cmask + (size_t)b * kN;
    float v[13];
#pragma unroll
    for (int k = 0; k < 13; k++) {
        int n = lane + k * 32;
        v[k] = (n < kN) ? row[n] - 1e30f * (1.f - mrow[n]) : -INFINITY;
    }
    float mx = v[0];
#pragma unroll
    for (int k = 1; k < 13; k++) mx = fmaxf(mx, v[k]);
#pragma unroll
    for (int o = 16; o; o >>= 1) mx = fmaxf(mx, __shfl_xor_sync(0xffffffff, mx, o));
    float s = 0.f;
    float e[13];
#pragma unroll
    for (int k = 0; k < 13; k++) {
        int n = lane + k * 32;
        e[k] = (n < kN) ? __expf(v[k] - mx) : 0.f;
        s += e[k];
    }
#pragma unroll
    for (int o = 16; o; o >>= 1) s += __shfl_xor_sync(0xffffffff, s, o);
    float r = 1.f / s;
    float* orow = g_Sc + (size_t)w * kN;
#pragma unroll
    for (int k = 0; k < 13; k++) {
        int n = lane + k * 32;
        if (n < kN) orow[n] = e[k] * r;
    }
}

// U[b][m][d] = sum_n Sc[b][m][n] * Ct[b][n][d].  One block per batch.
__global__ void __launch_bounds__(512) k_U(const float* __restrict__ Ct) {
    int b = blockIdx.x;
    int tid = threadIdx.x;
    int d = tid & 127;
    int mq = tid >> 7;  // 0..3, each owns 14 m-slots (padded to 56)
    __shared__ float cts[16][128];
    __shared__ float scs[16][56];
    u64 acc[7] = {0, 0, 0, 0, 0, 0, 0};

    for (int n0 = 0; n0 < kN; n0 += 16) {
#pragma unroll
        for (int r = 0; r < 4; r++) {
            int idx = tid + r * 512;
            int n = idx >> 7, dd = idx & 127;
            cts[n][dd] = Ct[((size_t)b * kN + n0 + n) * 128 + dd];
        }
        for (int idx = tid; idx < 16 * 56; idx += 512) {
            int n = idx & 15;
            int m = idx >> 4;
            scs[n][m] = (m < kM) ? g_Sc[((size_t)b * kM + m) * kN + n0 + n] : 0.f;
        }
        __syncthreads();
#pragma unroll
        for (int n = 0; n < 16; n++) {
            float ct = cts[n][d];
            u64 c2 = pk2(ct, ct);
            const u64* sp = (const u64*)&scs[n][mq * 14];
#pragma unroll
            for (int j = 0; j < 7; j++) acc[j] = fma2(c2, sp[j], acc[j]);
        }
        __syncthreads();
    }
#pragma unroll
    for (int j = 0; j < 7; j++) {
        float v0, v1;
        upk2(acc[j], v0, v1);
        int m = mq * 14 + 2 * j;
        if (m < kM) g_U[((size_t)b * kM + m) * 128 + d] = v0;
        if (m + 1 < kM) g_U[((size_t)b * kM + m + 1) * 128 + d] = v1;
    }
}

// Output: block handles (b, 16 n's); A & Bt via smem-staged Sr, coalesced Qt/U.
__global__ void __launch_bounds__(256) k_out(const float* __restrict__ Ct,
                                             float* __restrict__ out) {
    int b = blockIdx.x / 25;
    int n0 = (blockIdx.x % 25) * 16;
    int tid = threadIdx.x;
    int d = tid & 127;
    int nq = tid >> 7;  // 0/1: 8 n's each
    __shared__ float srs[kM][16];
    for (int idx = tid; idx < kM * 16; idx += 256) {
        int m = idx >> 4, nj = idx & 15;
        srs[m][nj] = g_Sr[((size_t)b * kM + m) * kN + n0 + nj];
    }
    __syncthreads();
    u64 a2[4] = {0, 0, 0, 0};
    u64 b2[4] = {0, 0, 0, 0};
    for (int m = 0; m < kM; m++) {
        float qv = g_Qt[((size_t)b * kM + m) * 128 + d];
        float uv = g_U[((size_t)b * kM + m) * 128 + d];
        u64 q2 = pk2(qv, qv), u2 = pk2(uv, uv);
        const u64* sp = (const u64*)&srs[m][nq * 8];
#pragma unroll
        for (int j = 0; j < 4; j++) {
            a2[j] = fma2(sp[j], q2, a2[j]);
            b2[j] = fma2(sp[j], u2, b2[j]);
        }
    }
#pragma unroll
    for (int j = 0; j < 4; j++) {
        float a0, a1, bt0, bt1;
        upk2(a2[j], a0, a1);
        upk2(b2[j], bt0, bt1);
#pragma unroll
        for (int t = 0; t < 2; t++) {
            int n = n0 + nq * 8 + 2 * j + t;
            float a = (t == 0) ? a0 : a1;
            float bt = (t == 0) ? bt0 : bt1;
            float c = Ct[((size_t)b * kN + n) * 128 + d];
            size_t base = ((size_t)b * kN + n) * 512;
            out[base + d] = c;
            out[base + 128 + d] = a;
            out[base + 256 + d] = c * a;
            out[base + 384 + d] = c * bt;
        }
    }
}

// ------------------------------- host side ---------------------------------
static inline int ceil_div(int a, int b) { return (a + b - 1) / b; }

extern "C" void kernel_launch(void* const* d_in, const int* in_sizes, int n_in,
                              void* d_out, int out_size) {
    (void)in_sizes; (void)n_in; (void)out_size;
    const float* ctx   = (const float*)d_in[0];
    const float* qst   = (const float*)d_in[1];
    const float* cmask = (const float*)d_in[2];
    const float* qmask = (const float*)d_in[3];
    const float* ln_g  = (const float*)d_in[4];
    const float* ln_b  = (const float*)d_in[5];
    const float* dww   = (const float*)d_in[6];
    const float* dwb   = (const float*)d_in[7];
    const float* pww   = (const float*)d_in[8];
    const float* pwb   = (const float*)d_in[9];
    const float* Wq    = (const float*)d_in[10];
    const float* bq    = (const float*)d_in[11];
    const float* Wk    = (const float*)d_in[12];
    const float* bk    = (const float*)d_in[13];
    const float* Wv    = (const float*)d_in[14];
    const float* bv    = (const float*)d_in[15];
    const float* Wo    = (const float*)d_in[16];
    const float* bo    = (const float*)d_in[17];
    const float* Wfc   = (const float*)d_in[18];
    const float* bfc   = (const float*)d_in[19];
    const float* cq_wc = (const float*)d_in[20];
    const float* cq_wq = (const float*)d_in[21];
    const float* cq_wm = (const float*)d_in[22];
    const float* cq_b  = (const float*)d_in[23];

    float *pC, *pQ, *pln, *pdw, *pqkv, *pao, *pcc, *pqq, *pCt, *pQt, *pQw;
    cudaGetSymbolAddress((void**)&pC, g_C);
    cudaGetSymbolAddress((void**)&pQ, g_Q);
    cudaGetSymbolAddress((void**)&pln, g_ln);
    cudaGetSymbolAddress((void**)&pdw, g_dw);
    cudaGetSymbolAddress((void**)&pqkv, g_qkv);
    cudaGetSymbolAddress((void**)&pao, g_ao);
    cudaGetSymbolAddress((void**)&pcc, g_cc);
    cudaGetSymbolAddress((void**)&pqq, g_qq);
    cudaGetSymbolAddress((void**)&pCt, g_Ct);
    cudaGetSymbolAddress((void**)&pQt, g_Qt);
    cudaGetSymbolAddress((void**)&pQw, g_Qw);
    float* pWqkv; cudaGetSymbolAddress((void**)&pWqkv, g_Wqkv);
    float* pbqkv; cudaGetSymbolAddress((void**)&pbqkv, g_bqkv);
    float* pS; cudaGetSymbolAddress((void**)&pS, g_S);

    k_pe<<<ceil_div(kD * kN, 256), 256>>>();
    k_pack_qkv<<<ceil_div(3 * 128 * 128, 256), 256>>>(Wq, Wk, Wv, bq, bk, bv);

    auto run_block = [&](const float* emb, float* act, const float* msk, int L) {
        int P = kB * kD * L;
        int lt = ceil_div(L, 32);
        k_add_pe<<<ceil_div(P, 256), 256>>>(emb, act, L);
        for (int i = 0; i < kNC; i++) {
            k_ln<<<ceil_div(kB * L, 32), 128>>>(act, pln, ln_g, ln_b, L);
            k_dw<<<ceil_div(P, 256), 256>>>(pln, pdw, dww + (size_t)i * kD * kKW,
                                            dwb + (size_t)i * kD, L);
            k_gemm<false, true, true><<<dim3(lt, 1, kB), 256>>>(
                pdw, pww + (size_t)i * kD * kD, pwb + (size_t)i * kD, act, act, L, kD);
        }
        k_ln<<<ceil_div(kB * L, 32), 128>>>(act, pln, ln_g, ln_b, L);
        k_gemm<false, false, false><<<dim3(lt, 3, kB), 256>>>(
            pln, pWqkv, pbqkv, nullptr, pqkv, L, 384);
        k_attn<<<dim3(ceil_div(L, 256), kB * kH), 256>>>(pqkv, msk, pao, L);
        k_gemm<true, false, true><<<dim3(lt, 1, kB), 256>>>(pao, Wo, bo, act, act, L, kD);
        k_ln<<<ceil_div(kB * L, 32), 128>>>(act, pln, ln_g, ln_b, L);
        k_gemm<false, false, true><<<dim3(lt, 1, kB), 256>>>(pln, Wfc, bfc, act, act, L, kD);
    };

    run_block(ctx, pC, cmask, kN);
    run_block(qst, pQ, qmask, kM);

    // --------- context-query attention ---------
    k_dot<<<ceil_div(kB * kN, 256), 256>>>(pC, cq_wc, pcc, kN);
    k_dot<<<ceil_div(kB * kM, 256), 256>>>(pQ, cq_wq, pqq, kM);
    k_trC<<<dim3(13, 4, kB), dim3(32, 8)>>>(pC, pCt, kN);
    k_trQ<<<dim3(2, 4, kB), dim3(32, 8)>>>(pQ, pQt, pQw, cq_wm);
    k_sgemm<<<dim3(13, kB), 256>>>(pC, pQw, pcc, pqq, cq_b, pS);
    k_smrow<<<ceil_div(kB * kN, 256), 256>>>(qmask);
    k_smcol<<<ceil_div(kB * kM * 32, 256), 256>>>(cmask);
    k_U<<<kB, 512>>>(pCt);
    k_out<<<kB * 25, 256>>>(pCt, (float*)d_out);
}

// round 3
// speedup vs baseline: 1.7226x; 1.1795x over previous
#include <cuda_runtime.h>
#include <math.h>

// ---------------------------------------------------------------------------
// QANet forward, fp32 with packed f32x2 FMA on sm_103a.
// LayerNorm fused: stats (mu, 1/(std+eps)) computed in producer epilogues,
// application folded into consumers (dw-conv, GEMM X loads).
// ---------------------------------------------------------------------------
#define kB 64
#define kD 128
#define kN 400
#define kM 50
#define kH 8
#define kKD 16
#define kNC 4
#define kKW 7
#define kPAD 3

typedef unsigned long long u64;

__device__ __forceinline__ u64 pk2(float lo, float hi) {
    u64 r; asm("mov.b64 %0,{%1,%2};" : "=l"(r) : "f"(lo), "f"(hi)); return r;
}
__device__ __forceinline__ void upk2(u64 v, float& lo, float& hi) {
    asm("mov.b64 {%0,%1},%2;" : "=f"(lo), "=f"(hi) : "l"(v));
}
__device__ __forceinline__ u64 fma2(u64 a, u64 b, u64 c) {
    u64 d; asm("fma.rn.f32x2 %0,%1,%2,%3;" : "=l"(d) : "l"(a), "l"(b), "l"(c)); return d;
}
__device__ __forceinline__ u64 mul2(u64 a, u64 b) {
    u64 d; asm("mul.rn.f32x2 %0,%1,%2;" : "=l"(d) : "l"(a), "l"(b)); return d;
}

// ------------------------- device scratch (static) -------------------------
__device__ float g_C[kB * kD * kN];
__device__ float g_Q[kB * kD * kM];
__device__ float g_dw[kB * kD * kN];
__device__ float g_qkv[kB * 3 * kD * kN];
__device__ float g_ao[kB * kD * kN];
__device__ float g_Wqkv[3 * kD * kD];
__device__ float g_bqkv[3 * kD];
__device__ float g_pe[kD * kN];
__device__ float g_mu[kB * kN];
__device__ float g_ri[kB * kN];
__device__ float g_S[kB * kM * kN];
__device__ float g_Sr[kB * kM * kN];
__device__ float g_Sc[kB * kM * kN];
__device__ float g_U[kB * kM * kD];
__device__ float g_Ct[kB * kN * kD];
__device__ float g_Qt[kB * kM * kD];
__device__ float g_Qw[kB * kM * kD];
__device__ float g_cc[kB * kN];
__device__ float g_qq[kB * kM];

// ------------------------------ PE table ----------------------------------
__global__ void k_pe() {
    int idx = blockIdx.x * blockDim.x + threadIdx.x;
    if (idx >= kD * kN) return;
    int d = idx / kN;
    int l = idx % kN;
    int d0 = d & ~1;
    double f = pow(10000.0, -(double)d0 / (double)kD);
    double a = (double)l * f;
    g_pe[idx] = (d & 1) ? (float)cos(a) : (float)sin(a);
}

// ----------------- add PE + compute LN stats in one pass -------------------
__global__ void __launch_bounds__(128) k_add_pe_stats(const float* __restrict__ x,
                                                      float* __restrict__ y,
                                                      float* __restrict__ omu,
                                                      float* __restrict__ ori, int L) {
    int tid = threadIdx.x;
    int lsub = tid & 31;
    int grp = tid >> 5;
    int pos = blockIdx.x * 32 + lsub;
    int P = kB * L;
    bool ok = pos < P;
    int b = ok ? pos / L : 0;
    int l = ok ? pos % L : 0;

    float s = 0.f, sq = 0.f;
    if (ok) {
        const float* xp = x + ((size_t)b * kD + grp * 32) * L + l;
        float* yp = y + ((size_t)b * kD + grp * 32) * L + l;
#pragma unroll
        for (int k = 0; k < 32; k++) {
            int d = grp * 32 + k;
            float v = xp[(size_t)k * L] + g_pe[d * kN + l];
            yp[(size_t)k * L] = v;
            s += v;
            sq += v * v;
        }
    }
    __shared__ float ss[4][32], sb[4][32];
    ss[grp][lsub] = s;
    sb[grp][lsub] = sq;
    __syncthreads();
    if (grp == 0 && ok) {
        float ts = ss[0][lsub] + ss[1][lsub] + ss[2][lsub] + ss[3][lsub];
        float tq = sb[0][lsub] + sb[1][lsub] + sb[2][lsub] + sb[3][lsub];
        float mu = ts * (1.f / 128.f);
        float var = (tq - 128.f * mu * mu) * (1.f / 127.f);
        var = fmaxf(var, 0.f);
        omu[pos] = mu;
        ori[pos] = 1.f / (sqrtf(var) + 1e-6f);
    }
}

// ------------------- depthwise conv with LN applied on the fly -------------
__global__ void k_dw(const float* __restrict__ x, float* __restrict__ y,
                     const float* __restrict__ w, const float* __restrict__ bias,
                     const float* __restrict__ gamma, const float* __restrict__ beta,
                     const float* __restrict__ mu, const float* __restrict__ ri, int L) {
    int idx = blockIdx.x * blockDim.x + threadIdx.x;
    if (idx >= kB * kD * L) return;
    int r = idx % (kD * L);
    int d = r / L;
    int l = r % L;
    int b = idx / (kD * L);
    const float* base = x + (size_t)(idx - l);
    const float* mup = mu + (size_t)b * L;
    const float* rip = ri + (size_t)b * L;
    float g = gamma[d], bt = beta[d];
    float a = bias[d];
#pragma unroll
    for (int k = 0; k < kKW; k++) {
        int j = l + k - kPAD;
        if (j >= 0 && j < L) {
            float xv = g * (base[j] - mup[j]) * rip[j] + bt;
            a += w[d * kKW + k] * xv;
        }
    }
    y[idx] = a;
}

// ------------------------------- GEMM --------------------------------------
// out[b, e, l] = act( sum_d W(e,d) * Xeff[b,d,l] + bias[e] ) (+ res[b,e,l])
// Xeff = LN(X) on-the-fly when LNX. Tile: 128 e x 64 l, thread = 8e x 4l.
// STATS: epilogue computes per-(b,l) LN stats of the written output.
template <bool TR, bool RELU, bool RES, bool LNX, bool STATS>
__global__ void __launch_bounds__(256) k_gemm(const float* __restrict__ X,
                                              const float* __restrict__ W,
                                              const float* __restrict__ bias,
                                              const float* res, float* out,
                                              int L, int Etot,
                                              const float* __restrict__ mu,
                                              const float* __restrict__ ri,
                                              const float* __restrict__ gamma,
                                              const float* __restrict__ beta,
                                              float* omu, float* ori) {
    __shared__ float Xs[32][68];
    __shared__ float Ws[32][132];
    __shared__ float mus[64], ris[64];
    __shared__ float gs[128], bs2[128];
    __shared__ float red1[16][68], red2[16][68];

    int tid = threadIdx.x;
    int eq = tid >> 4;   // 0..15 -> 8 e's each
    int lq = tid & 15;   // 0..15 -> 4 l's each
    int l0 = blockIdx.x * 64;
    int et = blockIdx.y * 128;
    int b = blockIdx.z;

    if (LNX) {
        if (tid < 64) {
            int p = l0 + tid;
            mus[tid] = (p < L) ? mu[(size_t)b * L + p] : 0.f;
            ris[tid] = (p < L) ? ri[(size_t)b * L + p] : 0.f;
        }
        if (tid < 128) {
            gs[tid] = gamma[tid];
            bs2[tid] = beta[tid];
        }
        __syncthreads();
    }

    u64 acc[16];
#pragma unroll
    for (int j = 0; j < 16; j++) acc[j] = 0;

    for (int d0 = 0; d0 < 128; d0 += 32) {
#pragma unroll
        for (int r = 0; r < 8; r++) {
            int idx = tid + r * 256;
            int dd = idx >> 6;
            int ll = idx & 63;
            int lg = l0 + ll;
            float v = 0.f;
            if (lg < L) {
                v = X[((size_t)b * 128 + d0 + dd) * L + lg];
                if (LNX) v = gs[d0 + dd] * (v - mus[ll]) * ris[ll] + bs2[d0 + dd];
            }
            Xs[dd][ll] = v;
        }
#pragma unroll
        for (int r = 0; r < 16; r++) {
            int idx = tid + r * 256;
            if (TR) {
                int dd = idx >> 7;
                int e = idx & 127;
                Ws[dd][e] = W[(size_t)(d0 + dd) * Etot + et + e];
            } else {
                int dd = idx & 31;
                int e = idx >> 5;
                Ws[dd][e] = W[(size_t)(et + e) * 128 + d0 + dd];
            }
        }
        __syncthreads();
#pragma unroll
        for (int dd = 0; dd < 32; dd++) {
            float4 xv = *(const float4*)&Xs[dd][lq * 4];
            u64 x0 = pk2(xv.x, xv.x), x1 = pk2(xv.y, xv.y);
            u64 x2 = pk2(xv.z, xv.z), x3 = pk2(xv.w, xv.w);
            const ulonglong2* wp = (const ulonglong2*)&Ws[dd][eq * 8];
            ulonglong2 wa = wp[0], wb = wp[1];
            acc[0] = fma2(wa.x, x0, acc[0]);
            acc[1] = fma2(wa.x, x1, acc[1]);
            acc[2] = fma2(wa.x, x2, acc[2]);
            acc[3] = fma2(wa.x, x3, acc[3]);
            acc[4] = fma2(wa.y, x0, acc[4]);
            acc[5] = fma2(wa.y, x1, acc[5]);
            acc[6] = fma2(wa.y, x2, acc[6]);
            acc[7] = fma2(wa.y, x3, acc[7]);
            acc[8] = fma2(wb.x, x0, acc[8]);
            acc[9] = fma2(wb.x, x1, acc[9]);
            acc[10] = fma2(wb.x, x2, acc[10]);
            acc[11] = fma2(wb.x, x3, acc[11]);
            acc[12] = fma2(wb.y, x0, acc[12]);
            acc[13] = fma2(wb.y, x1, acc[13]);
            acc[14] = fma2(wb.y, x2, acc[14]);
            acc[15] = fma2(wb.y, x3, acc[15]);
        }
        __syncthreads();
    }

    float sum_l[4] = {0.f, 0.f, 0.f, 0.f};
    float sq_l[4] = {0.f, 0.f, 0.f, 0.f};
#pragma unroll
    for (int p = 0; p < 4; p++) {
        int e0 = et + eq * 8 + 2 * p;
        float b0v = bias[e0], b1v = bias[e0 + 1];
#pragma unroll
        for (int q = 0; q < 4; q++) {
            float v0, v1;
            upk2(acc[p * 4 + q], v0, v1);
            v0 += b0v;
            v1 += b1v;
            if (RELU) { v0 = fmaxf(v0, 0.f); v1 = fmaxf(v1, 0.f); }
            int lg = l0 + lq * 4 + q;
            if (lg < L) {
                size_t oi0 = ((size_t)b * Etot + e0) * L + lg;
                size_t oi1 = oi0 + L;
                if (RES) { v0 += res[oi0]; v1 += res[oi1]; }
                out[oi0] = v0;
                out[oi1] = v1;
            }
            if (STATS) {
                sum_l[q] += v0 + v1;
                sq_l[q] += v0 * v0 + v1 * v1;
            }
        }
    }
    if (STATS) {
#pragma unroll
        for (int q = 0; q < 4; q++) {
            red1[eq][lq * 4 + q] = sum_l[q];
            red2[eq][lq * 4 + q] = sq_l[q];
        }
        __syncthreads();
        if (tid < 64) {
            int lg = l0 + tid;
            if (lg < L) {
                float s = 0.f, ss = 0.f;
#pragma unroll
                for (int g = 0; g < 16; g++) {
                    s += red1[g][tid];
                    ss += red2[g][tid];
                }
                float muv = s * (1.f / 128.f);
                float var = (ss - 128.f * muv * muv) * (1.f / 127.f);
                var = fmaxf(var, 0.f);
                omu[(size_t)b * L + lg] = muv;
                ori[(size_t)b * L + lg] = 1.f / (sqrtf(var) + 1e-6f);
            }
        }
    }
}

// ----------------------------- QKV packing ---------------------------------
__global__ void k_pack_qkv(const float* __restrict__ Wq, const float* __restrict__ Wk,
                           const float* __restrict__ Wv, const float* __restrict__ bq,
                           const float* __restrict__ bk, const float* __restrict__ bv) {
    int idx = blockIdx.x * blockDim.x + threadIdx.x;
    if (idx < 3 * 128 * 128) {
        int e = idx >> 7;
        int d = idx & 127;
        int qv = e >> 7;
        int hk = e & 127;
        int h = hk >> 4;
        int kk = hk & 15;
        const float* src = (qv == 0) ? Wq : (qv == 1 ? Wk : Wv);
        g_Wqkv[idx] = src[((size_t)h * 128 + d) * 16 + kk];
    }
    if (idx < 384) {
        int qv = idx >> 7;
        int hk = idx & 127;
        const float* srcb = (qv == 0) ? bq : (qv == 1 ? bk : bv);
        g_bqkv[idx] = srcb[hk];
    }
}

// ----------------------------- attention core ------------------------------
// 8-key score batching: one acc rescale per 8 keys instead of per key.
__global__ void __launch_bounds__(256) k_attn(const float* __restrict__ qkv,
                                              const float* __restrict__ mask,
                                              float* __restrict__ o, int L) {
    const int KT = 64;
    __shared__ u64 ks[KT][9], vs[KT][9];
    __shared__ float ms[KT];
    int tid = threadIdx.x;
    int bh = blockIdx.y;
    int b = bh >> 3;
    int h = bh & 7;
    int i = blockIdx.x * 256 + tid;
    bool act = i < L;

    u64 q2[8];
    if (act) {
        const float* qp = qkv + ((size_t)b * 384 + h * 16) * L + i;
#pragma unroll
        for (int c = 0; c < 8; c++)
            q2[c] = pk2(qp[(size_t)(2 * c) * L] * 0.25f, qp[(size_t)(2 * c + 1) * L] * 0.25f);
    }
    float m = -INFINITY, lsum = 0.f;
    u64 acc[8] = {0, 0, 0, 0, 0, 0, 0, 0};

    for (int j0 = 0; j0 < L; j0 += KT) {
        int cnt = min(KT, L - j0);
        for (int idx = tid; idx < 8 * KT; idx += 256) {
            int c = idx >> 6;
            int t = idx & 63;
            if (t < cnt) {
                const float* kp = qkv + ((size_t)b * 384 + 128 + h * 16 + 2 * c) * L + j0 + t;
                ks[t][c] = pk2(kp[0], kp[(size_t)L]);
                const float* vp = kp + (size_t)128 * L;
                vs[t][c] = pk2(vp[0], vp[(size_t)L]);
            } else {
                ks[t][c] = 0;
                vs[t][c] = 0;
            }
        }
        if (tid < KT) ms[tid] = (tid < cnt) ? mask[(size_t)b * L + j0 + tid] : 0.f;
        __syncthreads();
        if (act) {
            for (int g = 0; g < cnt; g += 8) {
                float sreg[8];
#pragma unroll
                for (int t2 = 0; t2 < 8; t2++) {
                    int t = g + t2;
                    u64 s2 = 0;
#pragma unroll
                    for (int c = 0; c < 8; c++) s2 = fma2(q2[c], ks[t][c], s2);
                    float slo, shi;
                    upk2(s2, slo, shi);
                    sreg[t2] = slo + shi - 1e30f * (1.f - ms[t]);
                }
                float gm = sreg[0];
#pragma unroll
                for (int t2 = 1; t2 < 8; t2++) gm = fmaxf(gm, sreg[t2]);
                float nm = fmaxf(m, gm);
                float sc = __expf(m - nm);
                lsum *= sc;
                u64 scp = pk2(sc, sc);
#pragma unroll
                for (int c = 0; c < 8; c++) acc[c] = mul2(scp, acc[c]);
#pragma unroll
                for (int t2 = 0; t2 < 8; t2++) {
                    int t = g + t2;
                    float p = __expf(sreg[t2] - nm);
                    lsum += p;
                    u64 pp = pk2(p, p);
#pragma unroll
                    for (int c = 0; c < 8; c++) acc[c] = fma2(pp, vs[t][c], acc[c]);
                }
                m = nm;
            }
        }
        __syncthreads();
    }
    if (act) {
        float r = 1.f / lsum;
        float* op = o + ((size_t)b * 128 + h * 16) * L + i;
#pragma unroll
        for (int c = 0; c < 8; c++) {
            float lo, hi;
            upk2(acc[c], lo, hi);
            op[(size_t)(2 * c) * L] = lo * r;
            op[(size_t)(2 * c + 1) * L] = hi * r;
        }
    }
}

// ------------------------------ transposes ---------------------------------
__global__ void k_trC(const float* __restrict__ X, float* __restrict__ Y, int L) {
    __shared__ float t[32][33];
    int b = blockIdx.z, d0 = blockIdx.y * 32, l0 = blockIdx.x * 32;
    int tx = threadIdx.x, ty = threadIdx.y;
#pragma unroll
    for (int k = 0; k < 4; k++) {
        int l = l0 + tx;
        t[ty + 8 * k][tx] = (l < L) ? X[((size_t)b * 128 + d0 + ty + 8 * k) * L + l] : 0.f;
    }
    __syncthreads();
#pragma unroll
    for (int k = 0; k < 4; k++) {
        int l = l0 + ty + 8 * k;
        if (l < L) Y[((size_t)b * L + l) * 128 + d0 + tx] = t[tx][ty + 8 * k];
    }
}

__global__ void k_trQ(const float* __restrict__ X, float* __restrict__ Yt,
                      float* __restrict__ Yw, const float* __restrict__ wm) {
    __shared__ float t[32][33];
    int b = blockIdx.z, d0 = blockIdx.y * 32, l0 = blockIdx.x * 32;
    int tx = threadIdx.x, ty = threadIdx.y;
#pragma unroll
    for (int k = 0; k < 4; k++) {
        int l = l0 + tx;
        t[ty + 8 * k][tx] = (l < kM) ? X[((size_t)b * 128 + d0 + ty + 8 * k) * kM + l] : 0.f;
    }
    __syncthreads();
    float w = wm[d0 + tx];
#pragma unroll
    for (int k = 0; k < 4; k++) {
        int l = l0 + ty + 8 * k;
        if (l < kM) {
            float v = t[tx][ty + 8 * k];
            size_t oi = ((size_t)b * kM + l) * 128 + d0 + tx;
            Yt[oi] = v;
            Yw[oi] = v * w;
        }
    }
}

// ------------------------------ CQ attention -------------------------------
__global__ void k_dot(const float* __restrict__ X, const float* __restrict__ w,
                      float* __restrict__ out, int L) {
    int idx = blockIdx.x * blockDim.x + threadIdx.x;
    if (idx >= kB * L) return;
    int b = idx / L;
    int pos = idx % L;
    const float* xp = X + (size_t)b * kD * L + pos;
    float a = 0.f;
#pragma unroll 8
    for (int d = 0; d < kD; d++) a += w[d] * xp[(size_t)d * L];
    out[idx] = a;
}

// S[b][m][n] = sum_d Qw[b][m][d] * C[b][d][n] + cc[b][n] + qq[b][m] + b0
__global__ void __launch_bounds__(256) k_sgemm(const float* __restrict__ X,
                                               const float* __restrict__ Qw,
                                               const float* __restrict__ cc,
                                               const float* __restrict__ qq,
                                               const float* __restrict__ b0,
                                               float* __restrict__ S) {
    __shared__ float Xs[32][33];
    __shared__ float Ws[32][68];
    int tid = threadIdx.x;
    int l = tid & 31;
    int eg = tid >> 5;
    int l0 = blockIdx.x * 32;
    int b = blockIdx.y;
    u64 acc[4] = {0, 0, 0, 0};

    for (int d0 = 0; d0 < 128; d0 += 32) {
#pragma unroll
        for (int r = 0; r < 4; r++) {
            int idx = tid + r * 256;
            int dd = idx >> 5, ll = idx & 31;
            int lg = l0 + ll;
            Xs[dd][ll] = (lg < kN) ? X[((size_t)b * 128 + d0 + dd) * kN + lg] : 0.f;
        }
#pragma unroll
        for (int r = 0; r < 8; r++) {
            int idx = tid + r * 256;
            int dd = idx >> 6;
            int e = idx & 63;
            Ws[dd][e] = (e < kM) ? Qw[((size_t)b * kM + e) * 128 + d0 + dd] : 0.f;
        }
        __syncthreads();
#pragma unroll
        for (int dd = 0; dd < 32; dd++) {
            float xv = Xs[dd][l];
            u64 xx = pk2(xv, xv);
            const ulonglong2* wr = (const ulonglong2*)&Ws[dd][eg * 8];
            ulonglong2 w0 = wr[0], w1 = wr[1];
            acc[0] = fma2(xx, w0.x, acc[0]);
            acc[1] = fma2(xx, w0.y, acc[1]);
            acc[2] = fma2(xx, w1.x, acc[2]);
            acc[3] = fma2(xx, w1.y, acc[3]);
        }
        __syncthreads();
    }
    int lg = l0 + l;
    if (lg < kN) {
        float base = cc[b * kN + lg] + b0[0];
#pragma unroll
        for (int j = 0; j < 4; j++) {
            float v0, v1;
            upk2(acc[j], v0, v1);
            int e0 = eg * 8 + 2 * j;
            if (e0 < kM) S[((size_t)b * kM + e0) * kN + lg] = v0 + base + qq[b * kM + e0];
            if (e0 + 1 < kM) S[((size_t)b * kM + e0 + 1) * kN + lg] = v1 + base + qq[b * kM + e0 + 1];
        }
    }
}

__global__ void k_smrow(const float* __restrict__ qmask) {
    int idx = blockIdx.x * blockDim.x + threadIdx.x;
    if (idx >= kB * kN) return;
    int b = idx / kN;
    int n = idx % kN;
    float v[kM];
    float mx = -INFINITY;
#pragma unroll
    for (int m = 0; m < kM; m++) {
        v[m] = g_S[((size_t)b * kM + m) * kN + n] - 1e30f * (1.f - qmask[b * kM + m]);
        mx = fmaxf(mx, v[m]);
    }
    float s = 0.f;
#pragma unroll
    for (int m = 0; m < kM; m++) {
        v[m] = __expf(v[m] - mx);
        s += v[m];
    }
    float r = 1.f / s;
#pragma unroll
    for (int m = 0; m < kM; m++) g_Sr[((size_t)b * kM + m) * kN + n] = v[m] * r;
}

__global__ void k_smcol(const float* __restrict__ cmask) {
    int w = (blockIdx.x * blockDim.x + threadIdx.x) >> 5;
    int lane = threadIdx.x & 31;
    if (w >= kB * kM) return;
    int b = w / kM;
    const float* row = g_S + (size_t)w * kN;
    const float* mrow = cmask + (size_t)b * kN;
    float v[13];
#pragma unroll
    for (int k = 0; k < 13; k++) {
        int n = lane + k * 32;
        v[k] = (n < kN) ? row[n] - 1e30f * (1.f - mrow[n]) : -INFINITY;
    }
    float mx = v[0];
#pragma unroll
    for (int k = 1; k < 13; k++) mx = fmaxf(mx, v[k]);
#pragma unroll
    for (int o = 16; o; o >>= 1) mx = fmaxf(mx, __shfl_xor_sync(0xffffffff, mx, o));
    float s = 0.f;
    float e[13];
#pragma unroll
    for (int k = 0; k < 13; k++) {
        int n = lane + k * 32;
        e[k] = (n < kN) ? __expf(v[k] - mx) : 0.f;
        s += e[k];
    }
#pragma unroll
    for (int o = 16; o; o >>= 1) s += __shfl_xor_sync(0xffffffff, s, o);
    float r = 1.f / s;
    float* orow = g_Sc + (size_t)w * kN;
#pragma unroll
    for (int k = 0; k < 13; k++) {
        int n = lane + k * 32;
        if (n < kN) orow[n] = e[k] * r;
    }
}

// U[b][m][d] = sum_n Sc[b][m][n] * Ct[b][n][d]
__global__ void __launch_bounds__(512) k_U(const float* __restrict__ Ct) {
    int b = blockIdx.x;
    int tid = threadIdx.x;
    int d = tid & 127;
    int mq = tid >> 7;
    __shared__ float cts[16][128];
    __shared__ float scs[16][56];
    u64 acc[7] = {0, 0, 0, 0, 0, 0, 0};

    for (int n0 = 0; n0 < kN; n0 += 16) {
#pragma unroll
        for (int r = 0; r < 4; r++) {
            int idx = tid + r * 512;
            int n = idx >> 7, dd = idx & 127;
            cts[n][dd] = Ct[((size_t)b * kN + n0 + n) * 128 + dd];
        }
        for (int idx = tid; idx < 16 * 56; idx += 512) {
            int n = idx & 15;
            int m = idx >> 4;
            scs[n][m] = (m < kM) ? g_Sc[((size_t)b * kM + m) * kN + n0 + n] : 0.f;
        }
        __syncthreads();
#pragma unroll
        for (int n = 0; n < 16; n++) {
            float ct = cts[n][d];
            u64 c2 = pk2(ct, ct);
            const u64* sp = (const u64*)&scs[n][mq * 14];
#pragma unroll
            for (int j = 0; j < 7; j++) acc[j] = fma2(c2, sp[j], acc[j]);
        }
        __syncthreads();
    }
#pragma unroll
    for (int j = 0; j < 7; j++) {
        float v0, v1;
        upk2(acc[j], v0, v1);
        int m = mq * 14 + 2 * j;
        if (m < kM) g_U[((size_t)b * kM + m) * 128 + d] = v0;
        if (m + 1 < kM) g_U[((size_t)b * kM + m + 1) * 128 + d] = v1;
    }
}

__global__ void __launch_bounds__(256) k_out(const float* __restrict__ Ct,
                                             float* __restrict__ out) {
    int b = blockIdx.x / 25;
    int n0 = (blockIdx.x % 25) * 16;
    int tid = threadIdx.x;
    int d = tid & 127;
    int nq = tid >> 7;
    __shared__ float srs[kM][16];
    for (int idx = tid; idx < kM * 16; idx += 256) {
        int m = idx >> 4, nj = idx & 15;
        srs[m][nj] = g_Sr[((size_t)b * kM + m) * kN + n0 + nj];
    }
    __syncthreads();
    u64 a2[4] = {0, 0, 0, 0};
    u64 b2[4] = {0, 0, 0, 0};
    for (int m = 0; m < kM; m++) {
        float qv = g_Qt[((size_t)b * kM + m) * 128 + d];
        float uv = g_U[((size_t)b * kM + m) * 128 + d];
        u64 q2 = pk2(qv, qv), u2 = pk2(uv, uv);
        const u64* sp = (const u64*)&srs[m][nq * 8];
#pragma unroll
        for (int j = 0; j < 4; j++) {
            a2[j] = fma2(sp[j], q2, a2[j]);
            b2[j] = fma2(sp[j], u2, b2[j]);
        }
    }
#pragma unroll
    for (int j = 0; j < 4; j++) {
        float a0, a1, bt0, bt1;
        upk2(a2[j], a0, a1);
        upk2(b2[j], bt0, bt1);
#pragma unroll
        for (int t = 0; t < 2; t++) {
            int n = n0 + nq * 8 + 2 * j + t;
            float a = (t == 0) ? a0 : a1;
            float bt = (t == 0) ? bt0 : bt1;
            float c = Ct[((size_t)b * kN + n) * 128 + d];
            size_t base = ((size_t)b * kN + n) * 512;
            out[base + d] = c;
            out[base + 128 + d] = a;
            out[base + 256 + d] = c * a;
            out[base + 384 + d] = c * bt;
        }
    }
}

// ------------------------------- host side ---------------------------------
static inline int ceil_div(int a, int b) { return (a + b - 1) / b; }

extern "C" void kernel_launch(void* const* d_in, const int* in_sizes, int n_in,
                              void* d_out, int out_size) {
    (void)in_sizes; (void)n_in; (void)out_size;
    const float* ctx   = (const float*)d_in[0];
    const float* qst   = (const float*)d_in[1];
    const float* cmask = (const float*)d_in[2];
    const float* qmask = (const float*)d_in[3];
    const float* ln_g  = (const float*)d_in[4];
    const float* ln_b  = (const float*)d_in[5];
    const float* dww   = (const float*)d_in[6];
    const float* dwb   = (const float*)d_in[7];
    const float* pww   = (const float*)d_in[8];
    const float* pwb   = (const float*)d_in[9];
    const float* Wq    = (const float*)d_in[10];
    const float* bq    = (const float*)d_in[11];
    const float* Wk    = (const float*)d_in[12];
    const float* bk    = (const float*)d_in[13];
    const float* Wv    = (const float*)d_in[14];
    const float* bv    = (const float*)d_in[15];
    const float* Wo    = (const float*)d_in[16];
    const float* bo    = (const float*)d_in[17];
    const float* Wfc   = (const float*)d_in[18];
    const float* bfc   = (const float*)d_in[19];
    const float* cq_wc = (const float*)d_in[20];
    const float* cq_wq = (const float*)d_in[21];
    const float* cq_wm = (const float*)d_in[22];
    const float* cq_b  = (const float*)d_in[23];

    float *pC, *pQ, *pdw, *pqkv, *pao, *pcc, *pqq, *pCt, *pQt, *pQw, *pmu, *pri;
    cudaGetSymbolAddress((void**)&pC, g_C);
    cudaGetSymbolAddress((void**)&pQ, g_Q);
    cudaGetSymbolAddress((void**)&pdw, g_dw);
    cudaGetSymbolAddress((void**)&pqkv, g_qkv);
    cudaGetSymbolAddress((void**)&pao, g_ao);
    cudaGetSymbolAddress((void**)&pcc, g_cc);
    cudaGetSymbolAddress((void**)&pqq, g_qq);
    cudaGetSymbolAddress((void**)&pCt, g_Ct);
    cudaGetSymbolAddress((void**)&pQt, g_Qt);
    cudaGetSymbolAddress((void**)&pQw, g_Qw);
    cudaGetSymbolAddress((void**)&pmu, g_mu);
    cudaGetSymbolAddress((void**)&pri, g_ri);
    float* pWqkv; cudaGetSymbolAddress((void**)&pWqkv, g_Wqkv);
    float* pbqkv; cudaGetSymbolAddress((void**)&pbqkv, g_bqkv);
    float* pS; cudaGetSymbolAddress((void**)&pS, g_S);

    k_pe<<<ceil_div(kD * kN, 256), 256>>>();
    k_pack_qkv<<<ceil_div(3 * 128 * 128, 256), 256>>>(Wq, Wk, Wv, bq, bk, bv);

    auto run_block = [&](const float* emb, float* act, const float* msk, int L) {
        int P = kB * kD * L;
        int lt = ceil_div(L, 64);
        k_add_pe_stats<<<ceil_div(kB * L, 32), 128>>>(emb, act, pmu, pri, L);
        for (int i = 0; i < kNC; i++) {
            k_dw<<<ceil_div(P, 256), 256>>>(act, pdw, dww + (size_t)i * kD * kKW,
                                            dwb + (size_t)i * kD, ln_g, ln_b, pmu, pri, L);
            // pw GEMM: relu + residual, epilogue computes stats for next LN
            k_gemm<false, true, true, false, true><<<dim3(lt, 1, kB), 256>>>(
                pdw, pww + (size_t)i * kD * kD, pwb + (size_t)i * kD, act, act, L, kD,
                nullptr, nullptr, nullptr, nullptr, pmu, pri);
        }
        // QKV GEMM with LN applied to X on the fly
        k_gemm<false, false, false, true, false><<<dim3(lt, 3, kB), 256>>>(
            act, pWqkv, pbqkv, nullptr, pqkv, L, 384, pmu, pri, ln_g, ln_b, nullptr, nullptr);
        k_attn<<<dim3(ceil_div(L, 256), kB * kH), 256>>>(pqkv, msk, pao, L);
        // Wo GEMM (transposed W) + residual, stats for FFN LN
        k_gemm<true, false, true, false, true><<<dim3(lt, 1, kB), 256>>>(
            pao, Wo, bo, act, act, L, kD, nullptr, nullptr, nullptr, nullptr, pmu, pri);
        // FFN GEMM with LN on X, residual, in-place
        k_gemm<false, false, true, true, false><<<dim3(lt, 1, kB), 256>>>(
            act, Wfc, bfc, act, act, L, kD, pmu, pri, ln_g, ln_b, nullptr, nullptr);
    };

    run_block(ctx, pC, cmask, kN);
    run_block(qst, pQ, qmask, kM);

    // --------- context-query attention ---------
    k_dot<<<ceil_div(kB * kN, 256), 256>>>(pC, cq_wc, pcc, kN);
    k_dot<<<ceil_div(kB * kM, 256), 256>>>(pQ, cq_wq, pqq, kM);
    k_trC<<<dim3(13, 4, kB), dim3(32, 8)>>>(pC, pCt, kN);
    k_trQ<<<dim3(2, 4, kB), dim3(32, 8)>>>(pQ, pQt, pQw, cq_wm);
    k_sgemm<<<dim3(13, kB), 256>>>(pC, pQw, pcc, pqq, cq_b, pS);
    k_smrow<<<ceil_div(kB * kN, 256), 256>>>(qmask);
    k_smcol<<<ceil_div(kB * kM * 32, 256), 256>>>(cmask);
    k_U<<<kB, 512>>>(pCt);
    k_out<<<kB * 25, 256>>>(pCt, (float*)d_out);
}

// round 4
// speedup vs baseline: 1.7315x; 1.0052x over previous
#include <cuda_runtime.h>
#include <math.h>

// ---------------------------------------------------------------------------
// QANet forward, fp32 / f32x2 on sm_103a.
// LN fused into consumers; depthwise conv fused into pointwise GEMM loader.
// ---------------------------------------------------------------------------
#define kB 64
#define kD 128
#define kN 400
#define kM 50
#define kH 8
#define kKD 16
#define kNC 4
#define kKW 7
#define kPAD 3

typedef unsigned long long u64;

__device__ __forceinline__ u64 pk2(float lo, float hi) {
    u64 r; asm("mov.b64 %0,{%1,%2};" : "=l"(r) : "f"(lo), "f"(hi)); return r;
}
__device__ __forceinline__ void upk2(u64 v, float& lo, float& hi) {
    asm("mov.b64 {%0,%1},%2;" : "=f"(lo), "=f"(hi) : "l"(v));
}
__device__ __forceinline__ u64 fma2(u64 a, u64 b, u64 c) {
    u64 d; asm("fma.rn.f32x2 %0,%1,%2,%3;" : "=l"(d) : "l"(a), "l"(b), "l"(c)); return d;
}
__device__ __forceinline__ u64 mul2(u64 a, u64 b) {
    u64 d; asm("mul.rn.f32x2 %0,%1,%2;" : "=l"(d) : "l"(a), "l"(b)); return d;
}

// ------------------------- device scratch (static) -------------------------
__device__ float g_C[kB * kD * kN];
__device__ float g_Q[kB * kD * kM];
__device__ float g_dw[kB * kD * kN];     // ping-pong partner for conv layers
__device__ float g_Q2[kB * kD * kM];     // ping-pong partner (question)
__device__ float g_qkv[kB * 3 * kD * kN];
__device__ float g_ao[kB * kD * kN];
__device__ float g_Wqkv[3 * kD * kD];
__device__ float g_bqkv[3 * kD];
__device__ float g_pe[kD * kN];
__device__ float g_mu[kB * kN];
__device__ float g_ri[kB * kN];
__device__ float g_S[kB * kM * kN];
__device__ float g_Sr[kB * kM * kN];
__device__ float g_Sc[kB * kM * kN];
__device__ float g_U[kB * kM * kD];
__device__ float g_Ct[kB * kN * kD];
__device__ float g_Qt[kB * kM * kD];
__device__ float g_Qw[kB * kM * kD];
__device__ float g_cc[kB * kN];
__device__ float g_qq[kB * kM];

// ------------------------------ PE table ----------------------------------
__global__ void k_pe() {
    int idx = blockIdx.x * blockDim.x + threadIdx.x;
    if (idx >= kD * kN) return;
    int d = idx / kN;
    int l = idx % kN;
    int d0 = d & ~1;
    double f = pow(10000.0, -(double)d0 / (double)kD);
    double a = (double)l * f;
    g_pe[idx] = (d & 1) ? (float)cos(a) : (float)sin(a);
}

// ----------------- add PE + compute LN stats in one pass -------------------
__global__ void __launch_bounds__(128) k_add_pe_stats(const float* __restrict__ x,
                                                      float* __restrict__ y,
                                                      float* __restrict__ omu,
                                                      float* __restrict__ ori, int L) {
    int tid = threadIdx.x;
    int lsub = tid & 31;
    int grp = tid >> 5;
    int pos = blockIdx.x * 32 + lsub;
    int P = kB * L;
    bool ok = pos < P;
    int b = ok ? pos / L : 0;
    int l = ok ? pos % L : 0;

    float s = 0.f, sq = 0.f;
    if (ok) {
        const float* xp = x + ((size_t)b * kD + grp * 32) * L + l;
        float* yp = y + ((size_t)b * kD + grp * 32) * L + l;
#pragma unroll
        for (int k = 0; k < 32; k++) {
            int d = grp * 32 + k;
            float v = xp[(size_t)k * L] + g_pe[d * kN + l];
            yp[(size_t)k * L] = v;
            s += v;
            sq += v * v;
        }
    }
    __shared__ float ss[4][32], sb[4][32];
    ss[grp][lsub] = s;
    sb[grp][lsub] = sq;
    __syncthreads();
    if (grp == 0 && ok) {
        float ts = ss[0][lsub] + ss[1][lsub] + ss[2][lsub] + ss[3][lsub];
        float tq = sb[0][lsub] + sb[1][lsub] + sb[2][lsub] + sb[3][lsub];
        float mu = ts * (1.f / 128.f);
        float var = (tq - 128.f * mu * mu) * (1.f / 127.f);
        var = fmaxf(var, 0.f);
        omu[pos] = mu;
        ori[pos] = 1.f / (sqrtf(var) + 1e-6f);
    }
}

// ---------------- fused LN + depthwise conv + pointwise GEMM ----------------
// out[b,e,l] = relu( sum_d Wpw(e,d) * conv(LN(X))[b,d,l] + pwb[e] ) + X[b,e,l]
// Epilogue computes LN stats of out. X read from actIn, out written to actOut.
__global__ void __launch_bounds__(256) k_cgemm(const float* __restrict__ X,
                                               const float* __restrict__ Wpw,
                                               const float* __restrict__ pwb,
                                               const float* __restrict__ cw,   // [128][7]
                                               const float* __restrict__ cb,   // [128]
                                               const float* __restrict__ gamma,
                                               const float* __restrict__ beta,
                                               const float* __restrict__ mu,
                                               const float* __restrict__ ri,
                                               float* __restrict__ out,
                                               float* __restrict__ omu,
                                               float* __restrict__ ori, int L) {
    __shared__ float Xl[32][72];   // LN'd halo tile: ll 0..69 -> gl = l0+ll-3
    __shared__ float Xs[32][68];   // conv output tile
    __shared__ float Ws[32][132];
    __shared__ float mus[72], ris[72];
    __shared__ float gs[128], bs2[128];
    __shared__ float cws[128][8];
    __shared__ float red1[16][68], red2[16][68];

    int tid = threadIdx.x;
    int eq = tid >> 4;   // 8 e's
    int lq = tid & 15;   // 4 l's
    int l0 = blockIdx.x * 64;
    int b = blockIdx.z;

    if (tid < 70) {
        int gl = l0 + tid - 3;
        bool in = (gl >= 0 && gl < L);
        mus[tid] = in ? mu[(size_t)b * L + gl] : 0.f;
        ris[tid] = in ? ri[(size_t)b * L + gl] : 0.f;
    }
    if (tid < 128) {
        gs[tid] = gamma[tid];
        bs2[tid] = beta[tid];
#pragma unroll
        for (int k = 0; k < 7; k++) cws[tid][k] = cw[tid * 7 + k];
        cws[tid][7] = cb[tid];
    }
    __syncthreads();

    u64 acc[16];
#pragma unroll
    for (int j = 0; j < 16; j++) acc[j] = 0;

    for (int d0 = 0; d0 < 128; d0 += 32) {
        // 1) LN'd halo tile
        for (int idx = tid; idx < 32 * 70; idx += 256) {
            int dd = idx / 70;
            int ll = idx % 70;
            int gl = l0 + ll - 3;
            float v = 0.f;
            if (gl >= 0 && gl < L) {
                float xv = X[((size_t)b * 128 + d0 + dd) * L + gl];
                v = gs[d0 + dd] * (xv - mus[ll]) * ris[ll] + bs2[d0 + dd];
            }
            Xl[dd][ll] = v;
        }
        // pw weights (independent of Xl)
#pragma unroll
        for (int r = 0; r < 16; r++) {
            int idx = tid + r * 256;
            int dd = idx & 31;
            int e = idx >> 5;
            Ws[dd][e] = Wpw[(size_t)e * 128 + d0 + dd];
        }
        __syncthreads();
        // 2) depthwise conv from smem
#pragma unroll
        for (int r = 0; r < 8; r++) {
            int idx = tid + r * 256;
            int dd = idx >> 6;
            int ll = idx & 63;
            int d = d0 + dd;
            float a = cws[d][7];
#pragma unroll
            for (int k = 0; k < 7; k++) a += cws[d][k] * Xl[dd][ll + k];
            Xs[dd][ll] = a;
        }
        __syncthreads();
        // 3) main fma2 loop
#pragma unroll
        for (int dd = 0; dd < 32; dd++) {
            float4 xv = *(const float4*)&Xs[dd][lq * 4];
            u64 x0 = pk2(xv.x, xv.x), x1 = pk2(xv.y, xv.y);
            u64 x2 = pk2(xv.z, xv.z), x3 = pk2(xv.w, xv.w);
            const ulonglong2* wp = (const ulonglong2*)&Ws[dd][eq * 8];
            ulonglong2 wa = wp[0], wb = wp[1];
            acc[0] = fma2(wa.x, x0, acc[0]);
            acc[1] = fma2(wa.x, x1, acc[1]);
            acc[2] = fma2(wa.x, x2, acc[2]);
            acc[3] = fma2(wa.x, x3, acc[3]);
            acc[4] = fma2(wa.y, x0, acc[4]);
            acc[5] = fma2(wa.y, x1, acc[5]);
            acc[6] = fma2(wa.y, x2, acc[6]);
            acc[7] = fma2(wa.y, x3, acc[7]);
            acc[8] = fma2(wb.x, x0, acc[8]);
            acc[9] = fma2(wb.x, x1, acc[9]);
            acc[10] = fma2(wb.x, x2, acc[10]);
            acc[11] = fma2(wb.x, x3, acc[11]);
            acc[12] = fma2(wb.y, x0, acc[12]);
            acc[13] = fma2(wb.y, x1, acc[13]);
            acc[14] = fma2(wb.y, x2, acc[14]);
            acc[15] = fma2(wb.y, x3, acc[15]);
        }
        __syncthreads();
    }

    float sum_l[4] = {0.f, 0.f, 0.f, 0.f};
    float sq_l[4] = {0.f, 0.f, 0.f, 0.f};
#pragma unroll
    for (int p = 0; p < 4; p++) {
        int e0 = eq * 8 + 2 * p;
        float b0v = pwb[e0], b1v = pwb[e0 + 1];
#pragma unroll
        for (int q = 0; q < 4; q++) {
            float v0, v1;
            upk2(acc[p * 4 + q], v0, v1);
            v0 = fmaxf(v0 + b0v, 0.f);
            v1 = fmaxf(v1 + b1v, 0.f);
            int lg = l0 + lq * 4 + q;
            if (lg < L) {
                size_t oi0 = ((size_t)b * 128 + e0) * L + lg;
                size_t oi1 = oi0 + L;
                v0 += X[oi0];
                v1 += X[oi1];
                out[oi0] = v0;
                out[oi1] = v1;
            }
            sum_l[q] += v0 + v1;
            sq_l[q] += v0 * v0 + v1 * v1;
        }
    }
#pragma unroll
    for (int q = 0; q < 4; q++) {
        red1[eq][lq * 4 + q] = sum_l[q];
        red2[eq][lq * 4 + q] = sq_l[q];
    }
    __syncthreads();
    if (tid < 64) {
        int lg = l0 + tid;
        if (lg < L) {
            float s = 0.f, ss = 0.f;
#pragma unroll
            for (int g = 0; g < 16; g++) {
                s += red1[g][tid];
                ss += red2[g][tid];
            }
            float muv = s * (1.f / 128.f);
            float var = (ss - 128.f * muv * muv) * (1.f / 127.f);
            var = fmaxf(var, 0.f);
            omu[(size_t)b * L + lg] = muv;
            ori[(size_t)b * L + lg] = 1.f / (sqrtf(var) + 1e-6f);
        }
    }
}

// ------------------------------- GEMM --------------------------------------
template <bool TR, bool RELU, bool RES, bool LNX, bool STATS>
__global__ void __launch_bounds__(256) k_gemm(const float* __restrict__ X,
                                              const float* __restrict__ W,
                                              const float* __restrict__ bias,
                                              const float* res, float* out,
                                              int L, int Etot,
                                              const float* __restrict__ mu,
                                              const float* __restrict__ ri,
                                              const float* __restrict__ gamma,
                                              const float* __restrict__ beta,
                                              float* omu, float* ori) {
    __shared__ float Xs[32][68];
    __shared__ float Ws[32][132];
    __shared__ float mus[64], ris[64];
    __shared__ float gs[128], bs2[128];
    __shared__ float red1[16][68], red2[16][68];

    int tid = threadIdx.x;
    int eq = tid >> 4;
    int lq = tid & 15;
    int l0 = blockIdx.x * 64;
    int et = blockIdx.y * 128;
    int b = blockIdx.z;

    if (LNX) {
        if (tid < 64) {
            int p = l0 + tid;
            mus[tid] = (p < L) ? mu[(size_t)b * L + p] : 0.f;
            ris[tid] = (p < L) ? ri[(size_t)b * L + p] : 0.f;
        }
        if (tid < 128) {
            gs[tid] = gamma[tid];
            bs2[tid] = beta[tid];
        }
        __syncthreads();
    }

    u64 acc[16];
#pragma unroll
    for (int j = 0; j < 16; j++) acc[j] = 0;

    for (int d0 = 0; d0 < 128; d0 += 32) {
#pragma unroll
        for (int r = 0; r < 8; r++) {
            int idx = tid + r * 256;
            int dd = idx >> 6;
            int ll = idx & 63;
            int lg = l0 + ll;
            float v = 0.f;
            if (lg < L) {
                v = X[((size_t)b * 128 + d0 + dd) * L + lg];
                if (LNX) v = gs[d0 + dd] * (v - mus[ll]) * ris[ll] + bs2[d0 + dd];
            }
            Xs[dd][ll] = v;
        }
#pragma unroll
        for (int r = 0; r < 16; r++) {
            int idx = tid + r * 256;
            if (TR) {
                int dd = idx >> 7;
                int e = idx & 127;
                Ws[dd][e] = W[(size_t)(d0 + dd) * Etot + et + e];
            } else {
                int dd = idx & 31;
                int e = idx >> 5;
                Ws[dd][e] = W[(size_t)(et + e) * 128 + d0 + dd];
            }
        }
        __syncthreads();
#pragma unroll
        for (int dd = 0; dd < 32; dd++) {
            float4 xv = *(const float4*)&Xs[dd][lq * 4];
            u64 x0 = pk2(xv.x, xv.x), x1 = pk2(xv.y, xv.y);
            u64 x2 = pk2(xv.z, xv.z), x3 = pk2(xv.w, xv.w);
            const ulonglong2* wp = (const ulonglong2*)&Ws[dd][eq * 8];
            ulonglong2 wa = wp[0], wb = wp[1];
            acc[0] = fma2(wa.x, x0, acc[0]);
            acc[1] = fma2(wa.x, x1, acc[1]);
            acc[2] = fma2(wa.x, x2, acc[2]);
            acc[3] = fma2(wa.x, x3, acc[3]);
            acc[4] = fma2(wa.y, x0, acc[4]);
            acc[5] = fma2(wa.y, x1, acc[5]);
            acc[6] = fma2(wa.y, x2, acc[6]);
            acc[7] = fma2(wa.y, x3, acc[7]);
            acc[8] = fma2(wb.x, x0, acc[8]);
            acc[9] = fma2(wb.x, x1, acc[9]);
            acc[10] = fma2(wb.x, x2, acc[10]);
            acc[11] = fma2(wb.x, x3, acc[11]);
            acc[12] = fma2(wb.y, x0, acc[12]);
            acc[13] = fma2(wb.y, x1, acc[13]);
            acc[14] = fma2(wb.y, x2, acc[14]);
            acc[15] = fma2(wb.y, x3, acc[15]);
        }
        __syncthreads();
    }

    float sum_l[4] = {0.f, 0.f, 0.f, 0.f};
    float sq_l[4] = {0.f, 0.f, 0.f, 0.f};
#pragma unroll
    for (int p = 0; p < 4; p++) {
        int e0 = et + eq * 8 + 2 * p;
        float b0v = bias[e0], b1v = bias[e0 + 1];
#pragma unroll
        for (int q = 0; q < 4; q++) {
            float v0, v1;
            upk2(acc[p * 4 + q], v0, v1);
            v0 += b0v;
            v1 += b1v;
            if (RELU) { v0 = fmaxf(v0, 0.f); v1 = fmaxf(v1, 0.f); }
            int lg = l0 + lq * 4 + q;
            if (lg < L) {
                size_t oi0 = ((size_t)b * Etot + e0) * L + lg;
                size_t oi1 = oi0 + L;
                if (RES) { v0 += res[oi0]; v1 += res[oi1]; }
                out[oi0] = v0;
                out[oi1] = v1;
            }
            if (STATS) {
                sum_l[q] += v0 + v1;
                sq_l[q] += v0 * v0 + v1 * v1;
            }
        }
    }
    if (STATS) {
#pragma unroll
        for (int q = 0; q < 4; q++) {
            red1[eq][lq * 4 + q] = sum_l[q];
            red2[eq][lq * 4 + q] = sq_l[q];
        }
        __syncthreads();
        if (tid < 64) {
            int lg = l0 + tid;
            if (lg < L) {
                float s = 0.f, ss = 0.f;
#pragma unroll
                for (int g = 0; g < 16; g++) {
                    s += red1[g][tid];
                    ss += red2[g][tid];
                }
                float muv = s * (1.f / 128.f);
                float var = (ss - 128.f * muv * muv) * (1.f / 127.f);
                var = fmaxf(var, 0.f);
                omu[(size_t)b * L + lg] = muv;
                ori[(size_t)b * L + lg] = 1.f / (sqrtf(var) + 1e-6f);
            }
        }
    }
}

// ----------------------------- QKV packing ---------------------------------
__global__ void k_pack_qkv(const float* __restrict__ Wq, const float* __restrict__ Wk,
                           const float* __restrict__ Wv, const float* __restrict__ bq,
                           const float* __restrict__ bk, const float* __restrict__ bv) {
    int idx = blockIdx.x * blockDim.x + threadIdx.x;
    if (idx < 3 * 128 * 128) {
        int e = idx >> 7;
        int d = idx & 127;
        int qv = e >> 7;
        int hk = e & 127;
        int h = hk >> 4;
        int kk = hk & 15;
        const float* src = (qv == 0) ? Wq : (qv == 1 ? Wk : Wv);
        g_Wqkv[idx] = src[((size_t)h * 128 + d) * 16 + kk];
    }
    if (idx < 384) {
        int qv = idx >> 7;
        int hk = idx & 127;
        const float* srcb = (qv == 0) ? bq : (qv == 1 ? bk : bv);
        g_bqkv[idx] = srcb[hk];
    }
}

// ----------------------------- attention core ------------------------------
__global__ void __launch_bounds__(256) k_attn(const float* __restrict__ qkv,
                                              const float* __restrict__ mask,
                                              float* __restrict__ o, int L) {
    const int KT = 64;
    __shared__ u64 ks[KT][9], vs[KT][9];
    __shared__ float ms[KT];
    int tid = threadIdx.x;
    int bh = blockIdx.y;
    int b = bh >> 3;
    int h = bh & 7;
    int i = blockIdx.x * 256 + tid;
    bool act = i < L;

    u64 q2[8];
    if (act) {
        const float* qp = qkv + ((size_t)b * 384 + h * 16) * L + i;
#pragma unroll
        for (int c = 0; c < 8; c++)
            q2[c] = pk2(qp[(size_t)(2 * c) * L] * 0.25f, qp[(size_t)(2 * c + 1) * L] * 0.25f);
    }
    float m = -INFINITY, lsum = 0.f;
    u64 acc[8] = {0, 0, 0, 0, 0, 0, 0, 0};

    for (int j0 = 0; j0 < L; j0 += KT) {
        int cnt = min(KT, L - j0);
        for (int idx = tid; idx < 8 * KT; idx += 256) {
            int c = idx >> 6;
            int t = idx & 63;
            if (t < cnt) {
                const float* kp = qkv + ((size_t)b * 384 + 128 + h * 16 + 2 * c) * L + j0 + t;
                ks[t][c] = pk2(kp[0], kp[(size_t)L]);
                const float* vp = kp + (size_t)128 * L;
                vs[t][c] = pk2(vp[0], vp[(size_t)L]);
            } else {
                ks[t][c] = 0;
                vs[t][c] = 0;
            }
        }
        if (tid < KT) ms[tid] = (tid < cnt) ? mask[(size_t)b * L + j0 + tid] : 0.f;
        __syncthreads();
        if (act) {
            for (int g = 0; g < cnt; g += 8) {
                float sreg[8];
#pragma unroll
                for (int t2 = 0; t2 < 8; t2++) {
                    int t = g + t2;
                    u64 s2 = 0;
#pragma unroll
                    for (int c = 0; c < 8; c++) s2 = fma2(q2[c], ks[t][c], s2);
                    float slo, shi;
                    upk2(s2, slo, shi);
                    sreg[t2] = slo + shi - 1e30f * (1.f - ms[t]);
                }
                float gm = sreg[0];
#pragma unroll
                for (int t2 = 1; t2 < 8; t2++) gm = fmaxf(gm, sreg[t2]);
                float nm = fmaxf(m, gm);
                float sc = __expf(m - nm);
                lsum *= sc;
                u64 scp = pk2(sc, sc);
#pragma unroll
                for (int c = 0; c < 8; c++) acc[c] = mul2(scp, acc[c]);
#pragma unroll
                for (int t2 = 0; t2 < 8; t2++) {
                    int t = g + t2;
                    float p = __expf(sreg[t2] - nm);
                    lsum += p;
                    u64 pp = pk2(p, p);
#pragma unroll
                    for (int c = 0; c < 8; c++) acc[c] = fma2(pp, vs[t][c], acc[c]);
                }
                m = nm;
            }
        }
        __syncthreads();
    }
    if (act) {
        float r = 1.f / lsum;
        float* op = o + ((size_t)b * 128 + h * 16) * L + i;
#pragma unroll
        for (int c = 0; c < 8; c++) {
            float lo, hi;
            upk2(acc[c], lo, hi);
            op[(size_t)(2 * c) * L] = lo * r;
            op[(size_t)(2 * c + 1) * L] = hi * r;
        }
    }
}

// ------------------------------ transposes ---------------------------------
__global__ void k_trC(const float* __restrict__ X, float* __restrict__ Y, int L) {
    __shared__ float t[32][33];
    int b = blockIdx.z, d0 = blockIdx.y * 32, l0 = blockIdx.x * 32;
    int tx = threadIdx.x, ty = threadIdx.y;
#pragma unroll
    for (int k = 0; k < 4; k++) {
        int l = l0 + tx;
        t[ty + 8 * k][tx] = (l < L) ? X[((size_t)b * 128 + d0 + ty + 8 * k) * L + l] : 0.f;
    }
    __syncthreads();
#pragma unroll
    for (int k = 0; k < 4; k++) {
        int l = l0 + ty + 8 * k;
        if (l < L) Y[((size_t)b * L + l) * 128 + d0 + tx] = t[tx][ty + 8 * k];
    }
}

__global__ void k_trQ(const float* __restrict__ X, float* __restrict__ Yt,
                      float* __restrict__ Yw, const float* __restrict__ wm) {
    __shared__ float t[32][33];
    int b = blockIdx.z, d0 = blockIdx.y * 32, l0 = blockIdx.x * 32;
    int tx = threadIdx.x, ty = threadIdx.y;
#pragma unroll
    for (int k = 0; k < 4; k++) {
        int l = l0 + tx;
        t[ty + 8 * k][tx] = (l < kM) ? X[((size_t)b * 128 + d0 + ty + 8 * k) * kM + l] : 0.f;
    }
    __syncthreads();
    float w = wm[d0 + tx];
#pragma unroll
    for (int k = 0; k < 4; k++) {
        int l = l0 + ty + 8 * k;
        if (l < kM) {
            float v = t[tx][ty + 8 * k];
            size_t oi = ((size_t)b * kM + l) * 128 + d0 + tx;
            Yt[oi] = v;
            Yw[oi] = v * w;
        }
    }
}

// ------------------------------ CQ attention -------------------------------
__global__ void k_dot(const float* __restrict__ X, const float* __restrict__ w,
                      float* __restrict__ out, int L) {
    int idx = blockIdx.x * blockDim.x + threadIdx.x;
    if (idx >= kB * L) return;
    int b = idx / L;
    int pos = idx % L;
    const float* xp = X + (size_t)b * kD * L + pos;
    float a = 0.f;
#pragma unroll 8
    for (int d = 0; d < kD; d++) a += w[d] * xp[(size_t)d * L];
    out[idx] = a;
}

__global__ void __launch_bounds__(256) k_sgemm(const float* __restrict__ X,
                                               const float* __restrict__ Qw,
                                               const float* __restrict__ cc,
                                               const float* __restrict__ qq,
                                               const float* __restrict__ b0,
                                               float* __restrict__ S) {
    __shared__ float Xs[32][33];
    __shared__ float Ws[32][68];
    int tid = threadIdx.x;
    int l = tid & 31;
    int eg = tid >> 5;
    int l0 = blockIdx.x * 32;
    int b = blockIdx.y;
    u64 acc[4] = {0, 0, 0, 0};

    for (int d0 = 0; d0 < 128; d0 += 32) {
#pragma unroll
        for (int r = 0; r < 4; r++) {
            int idx = tid + r * 256;
            int dd = idx >> 5, ll = idx & 31;
            int lg = l0 + ll;
            Xs[dd][ll] = (lg < kN) ? X[((size_t)b * 128 + d0 + dd) * kN + lg] : 0.f;
        }
#pragma unroll
        for (int r = 0; r < 8; r++) {
            int idx = tid + r * 256;
            int dd = idx >> 6;
            int e = idx & 63;
            Ws[dd][e] = (e < kM) ? Qw[((size_t)b * kM + e) * 128 + d0 + dd] : 0.f;
        }
        __syncthreads();
#pragma unroll
        for (int dd = 0; dd < 32; dd++) {
            float xv = Xs[dd][l];
            u64 xx = pk2(xv, xv);
            const ulonglong2* wr = (const ulonglong2*)&Ws[dd][eg * 8];
            ulonglong2 w0 = wr[0], w1 = wr[1];
            acc[0] = fma2(xx, w0.x, acc[0]);
            acc[1] = fma2(xx, w0.y, acc[1]);
            acc[2] = fma2(xx, w1.x, acc[2]);
            acc[3] = fma2(xx, w1.y, acc[3]);
        }
        __syncthreads();
    }
    int lg = l0 + l;
    if (lg < kN) {
        float base = cc[b * kN + lg] + b0[0];
#pragma unroll
        for (int j = 0; j < 4; j++) {
            float v0, v1;
            upk2(acc[j], v0, v1);
            int e0 = eg * 8 + 2 * j;
            if (e0 < kM) S[((size_t)b * kM + e0) * kN + lg] = v0 + base + qq[b * kM + e0];
            if (e0 + 1 < kM) S[((size_t)b * kM + e0 + 1) * kN + lg] = v1 + base + qq[b * kM + e0 + 1];
        }
    }
}

__global__ void k_smrow(const float* __restrict__ qmask) {
    int idx = blockIdx.x * blockDim.x + threadIdx.x;
    if (idx >= kB * kN) return;
    int b = idx / kN;
    int n = idx % kN;
    float v[kM];
    float mx = -INFINITY;
#pragma unroll
    for (int m = 0; m < kM; m++) {
        v[m] = g_S[((size_t)b * kM + m) * kN + n] - 1e30f * (1.f - qmask[b * kM + m]);
        mx = fmaxf(mx, v[m]);
    }
    float s = 0.f;
#pragma unroll
    for (int m = 0; m < kM; m++) {
        v[m] = __expf(v[m] - mx);
        s += v[m];
    }
    float r = 1.f / s;
#pragma unroll
    for (int m = 0; m < kM; m++) g_Sr[((size_t)b * kM + m) * kN + n] = v[m] * r;
}

__global__ void k_smcol(const float* __restrict__ cmask) {
    int w = (blockIdx.x * blockDim.x + threadIdx.x) >> 5;
    int lane = threadIdx.x & 31;
    if (w >= kB * kM) return;
    int b = w / kM;
    const float* row = g_S + (size_t)w * kN;
    const float* mrow = cmask + (size_t)b * kN;
    float v[13];
#pragma unroll
    for (int k = 0; k < 13; k++) {
        int n = lane + k * 32;
        v[k] = (n < kN) ? row[n] - 1e30f * (1.f - mrow[n]) : -INFINITY;
    }
    float mx = v[0];
#pragma unroll
    for (int k = 1; k < 13; k++) mx = fmaxf(mx, v[k]);
#pragma unroll
    for (int o = 16; o; o >>= 1) mx = fmaxf(mx, __shfl_xor_sync(0xffffffff, mx, o));
    float s = 0.f;
    float e[13];
#pragma unroll
    for (int k = 0; k < 13; k++) {
        int n = lane + k * 32;
        e[k] = (n < kN) ? __expf(v[k] - mx) : 0.f;
        s += e[k];
    }
#pragma unroll
    for (int o = 16; o; o >>= 1) s += __shfl_xor_sync(0xffffffff, s, o);
    float r = 1.f / s;
    float* orow = g_Sc + (size_t)w * kN;
#pragma unroll
    for (int k = 0; k < 13; k++) {
        int n = lane + k * 32;
        if (n < kN) orow[n] = e[k] * r;
    }
}

__global__ void __launch_bounds__(512) k_U(const float* __restrict__ Ct) {
    int b = blockIdx.x;
    int tid = threadIdx.x;
    int d = tid & 127;
    int mq = tid >> 7;
    __shared__ float cts[16][128];
    __shared__ float scs[16][56];
    u64 acc[7] = {0, 0, 0, 0, 0, 0, 0};

    for (int n0 = 0; n0 < kN; n0 += 16) {
#pragma unroll
        for (int r = 0; r < 4; r++) {
            int idx = tid + r * 512;
            int n = idx >> 7, dd = idx & 127;
            cts[n][dd] = Ct[((size_t)b * kN + n0 + n) * 128 + dd];
        }
        for (int idx = tid; idx < 16 * 56; idx += 512) {
            int n = idx & 15;
            int m = idx >> 4;
            scs[n][m] = (m < kM) ? g_Sc[((size_t)b * kM + m) * kN + n0 + n] : 0.f;
        }
        __syncthreads();
#pragma unroll
        for (int n = 0; n < 16; n++) {
            float ct = cts[n][d];
            u64 c2 = pk2(ct, ct);
            const u64* sp = (const u64*)&scs[n][mq * 14];
#pragma unroll
            for (int j = 0; j < 7; j++) acc[j] = fma2(c2, sp[j], acc[j]);
        }
        __syncthreads();
    }
#pragma unroll
    for (int j = 0; j < 7; j++) {
        float v0, v1;
        upk2(acc[j], v0, v1);
        int m = mq * 14 + 2 * j;
        if (m < kM) g_U[((size_t)b * kM + m) * 128 + d] = v0;
        if (m + 1 < kM) g_U[((size_t)b * kM + m + 1) * 128 + d] = v1;
    }
}

__global__ void __launch_bounds__(256) k_out(const float* __restrict__ Ct,
                                             float* __restrict__ out) {
    int b = blockIdx.x / 25;
    int n0 = (blockIdx.x % 25) * 16;
    int tid = threadIdx.x;
    int d = tid & 127;
    int nq = tid >> 7;
    __shared__ float srs[kM][16];
    for (int idx = tid; idx < kM * 16; idx += 256) {
        int m = idx >> 4, nj = idx & 15;
        srs[m][nj] = g_Sr[((size_t)b * kM + m) * kN + n0 + nj];
    }
    __syncthreads();
    u64 a2[4] = {0, 0, 0, 0};
    u64 b2[4] = {0, 0, 0, 0};
    for (int m = 0; m < kM; m++) {
        float qv = g_Qt[((size_t)b * kM + m) * 128 + d];
        float uv = g_U[((size_t)b * kM + m) * 128 + d];
        u64 q2 = pk2(qv, qv), u2 = pk2(uv, uv);
        const u64* sp = (const u64*)&srs[m][nq * 8];
#pragma unroll
        for (int j = 0; j < 4; j++) {
            a2[j] = fma2(sp[j], q2, a2[j]);
            b2[j] = fma2(sp[j], u2, b2[j]);
        }
    }
#pragma unroll
    for (int j = 0; j < 4; j++) {
        float a0, a1, bt0, bt1;
        upk2(a2[j], a0, a1);
        upk2(b2[j], bt0, bt1);
#pragma unroll
        for (int t = 0; t < 2; t++) {
            int n = n0 + nq * 8 + 2 * j + t;
            float a = (t == 0) ? a0 : a1;
            float bt = (t == 0) ? bt0 : bt1;
            float c = Ct[((size_t)b * kN + n) * 128 + d];
            size_t base = ((size_t)b * kN + n) * 512;
            out[base + d] = c;
            out[base + 128 + d] = a;
            out[base + 256 + d] = c * a;
            out[base + 384 + d] = c * bt;
        }
    }
}

// ------------------------------- host side ---------------------------------
static inline int ceil_div(int a, int b) { return (a + b - 1) / b; }

extern "C" void kernel_launch(void* const* d_in, const int* in_sizes, int n_in,
                              void* d_out, int out_size) {
    (void)in_sizes; (void)n_in; (void)out_size;
    const float* ctx   = (const float*)d_in[0];
    const float* qst   = (const float*)d_in[1];
    const float* cmask = (const float*)d_in[2];
    const float* qmask = (const float*)d_in[3];
    const float* ln_g  = (const float*)d_in[4];
    const float* ln_b  = (const float*)d_in[5];
    const float* dww   = (const float*)d_in[6];
    const float* dwb   = (const float*)d_in[7];
    const float* pww   = (const float*)d_in[8];
    const float* pwb   = (const float*)d_in[9];
    const float* Wq    = (const float*)d_in[10];
    const float* bq    = (const float*)d_in[11];
    const float* Wk    = (const float*)d_in[12];
    const float* bk    = (const float*)d_in[13];
    const float* Wv    = (const float*)d_in[14];
    const float* bv    = (const float*)d_in[15];
    const float* Wo    = (const float*)d_in[16];
    const float* bo    = (const float*)d_in[17];
    const float* Wfc   = (const float*)d_in[18];
    const float* bfc   = (const float*)d_in[19];
    const float* cq_wc = (const float*)d_in[20];
    const float* cq_wq = (const float*)d_in[21];
    const float* cq_wm = (const float*)d_in[22];
    const float* cq_b  = (const float*)d_in[23];

    float *pC, *pQ, *pdw, *pQ2, *pqkv, *pao, *pcc, *pqq, *pCt, *pQt, *pQw, *pmu, *pri;
    cudaGetSymbolAddress((void**)&pC, g_C);
    cudaGetSymbolAddress((void**)&pQ, g_Q);
    cudaGetSymbolAddress((void**)&pdw, g_dw);
    cudaGetSymbolAddress((void**)&pQ2, g_Q2);
    cudaGetSymbolAddress((void**)&pqkv, g_qkv);
    cudaGetSymbolAddress((void**)&pao, g_ao);
    cudaGetSymbolAddress((void**)&pcc, g_cc);
    cudaGetSymbolAddress((void**)&pqq, g_qq);
    cudaGetSymbolAddress((void**)&pCt, g_Ct);
    cudaGetSymbolAddress((void**)&pQt, g_Qt);
    cudaGetSymbolAddress((void**)&pQw, g_Qw);
    cudaGetSymbolAddress((void**)&pmu, g_mu);
    cudaGetSymbolAddress((void**)&pri, g_ri);
    float* pWqkv; cudaGetSymbolAddress((void**)&pWqkv, g_Wqkv);
    float* pbqkv; cudaGetSymbolAddress((void**)&pbqkv, g_bqkv);
    float* pS; cudaGetSymbolAddress((void**)&pS, g_S);

    k_pe<<<ceil_div(kD * kN, 256), 256>>>();
    k_pack_qkv<<<ceil_div(3 * 128 * 128, 256), 256>>>(Wq, Wk, Wv, bq, bk, bv);

    auto run_block = [&](const float* emb, float* act, float* alt, const float* msk, int L) {
        int lt = ceil_div(L, 64);
        k_add_pe_stats<<<ceil_div(kB * L, 32), 128>>>(emb, act, pmu, pri, L);
        float* bufs[2] = {act, alt};
        for (int i = 0; i < kNC; i++) {
            float* src = bufs[i & 1];
            float* dst = bufs[(i + 1) & 1];
            k_cgemm<<<dim3(lt, 1, kB), 256>>>(
                src, pww + (size_t)i * kD * kD, pwb + (size_t)i * kD,
                dww + (size_t)i * kD * kKW, dwb + (size_t)i * kD,
                ln_g, ln_b, pmu, pri, dst, pmu, pri, L);
        }
        // after 4 layers (even), activation is back in `act`
        k_gemm<false, false, false, true, false><<<dim3(lt, 3, kB), 256>>>(
            act, pWqkv, pbqkv, nullptr, pqkv, L, 384, pmu, pri, ln_g, ln_b, nullptr, nullptr);
        k_attn<<<dim3(ceil_div(L, 256), kB * kH), 256>>>(pqkv, msk, pao, L);
        k_gemm<true, false, true, false, true><<<dim3(lt, 1, kB), 256>>>(
            pao, Wo, bo, act, act, L, kD, nullptr, nullptr, nullptr, nullptr, pmu, pri);
        k_gemm<false, false, true, true, false><<<dim3(lt, 1, kB), 256>>>(
            act, Wfc, bfc, act, act, L, kD, pmu, pri, ln_g, ln_b, nullptr, nullptr);
    };

    run_block(ctx, pC, pdw, cmask, kN);
    run_block(qst, pQ, pQ2, qmask, kM);

    // --------- context-query attention ---------
    k_dot<<<ceil_div(kB * kN, 256), 256>>>(pC, cq_wc, pcc, kN);
    k_dot<<<ceil_div(kB * kM, 256), 256>>>(pQ, cq_wq, pqq, kM);
    k_trC<<<dim3(13, 4, kB), dim3(32, 8)>>>(pC, pCt, kN);
    k_trQ<<<dim3(2, 4, kB), dim3(32, 8)>>>(pQ, pQt, pQw, cq_wm);
    k_sgemm<<<dim3(13, kB), 256>>>(pC, pQw, pcc, pqq, cq_b, pS);
    k_smrow<<<ceil_div(kB * kN, 256), 256>>>(qmask);
    k_smcol<<<ceil_div(kB * kM * 32, 256), 256>>>(cmask);
    k_U<<<kB, 512>>>(pCt);
    k_out<<<kB * 25, 256>>>(pCt, (float*)d_out);
}